// round 2
// baseline (speedup 1.0000x reference)
#include <cuda_runtime.h>
#include <cuda_bf16.h>
#include <math.h>

#define NROWS 2048
#define EMBED 4096

// ---------------- scratch ----------------
__device__ float g_H[NROWS * EMBED];
__device__ float g_part[16 * NROWS * 64];
__device__ float g_EMB[NROWS * 64];
__device__ float g_XP[NROWS * 256];
__device__ float g_states[NROWS * 192];   // h1[64] c1[64] h2[32] c2[32]
__device__ float g_G[EMBED * 32];
__device__ float g_cvec[EMBED];
__device__ float g_cat1[NROWS * 128];
__device__ float g_cat2[NROWS * 96];
__device__ float g_gates2[NROWS * 128];
__device__ float g_Wcat1[256 * 128];
__device__ float g_Wcat2[128 * 96];
__device__ float g_b1c[256];
__device__ float g_b2c[128];

__device__ __forceinline__ float sigf(float x) { return 1.0f / (1.0f + __expf(-x)); }

// ---------------- SPP ----------------
__global__ void spp_kernel(const float* __restrict__ frames, float* __restrict__ pooled) {
    __shared__ float tmax[144];
    const int nc = blockIdx.x;
    const int n = nc / 3, c = nc % 3;
    const float* img = frames + (size_t)nc * 9216;
    const int tid = threadIdx.x;
    if (tid < 144) {
        const int ti = tid / 12, tj = tid % 12;
        const float* p = img + ti * 8 * 96 + tj * 8;
        float m = -3.402823466e38f;
#pragma unroll
        for (int r = 0; r < 8; r++) {
            float4 v0 = *(const float4*)(p + r * 96);
            float4 v1 = *(const float4*)(p + r * 96 + 4);
            m = fmaxf(m, fmaxf(fmaxf(v0.x, v0.y), fmaxf(v0.z, v0.w)));
            m = fmaxf(m, fmaxf(fmaxf(v1.x, v1.y), fmaxf(v1.z, v1.w)));
        }
        tmax[tid] = m;
    }
    __syncthreads();
    float* orow = pooled + (size_t)n * 90;
    if (tid < 16) {
        int i = tid / 4, j = tid % 4;
        float m = -3.402823466e38f;
        for (int a = 0; a < 3; a++) for (int b = 0; b < 3; b++)
            m = fmaxf(m, tmax[(i * 3 + a) * 12 + (j * 3 + b)]);
        orow[c * 16 + i * 4 + j] = m;
    } else if (tid < 25) {
        int q = tid - 16, i = q / 3, j = q % 3;
        float m = -3.402823466e38f;
        for (int a = 0; a < 4; a++) for (int b = 0; b < 4; b++)
            m = fmaxf(m, tmax[(i * 4 + a) * 12 + (j * 4 + b)]);
        orow[48 + c * 9 + i * 3 + j] = m;
    } else if (tid < 29) {
        int q = tid - 25, i = q / 2, j = q % 2;
        float m = -3.402823466e38f;
        for (int a = 0; a < 6; a++) for (int b = 0; b < 6; b++)
            m = fmaxf(m, tmax[(i * 6 + a) * 12 + (j * 6 + b)]);
        orow[75 + c * 4 + i * 2 + j] = m;
    } else if (tid == 29) {
        float m = -3.402823466e38f;
        for (int a = 0; a < 144; a++) m = fmaxf(m, tmax[a]);
        orow[87 + c] = m;
    }
}

// ---------------- prep ----------------
__global__ void prep_kernel(const float* __restrict__ spp_w, const float* __restrict__ spp_b,
                            const float* __restrict__ fw, const float* __restrict__ fb,
                            const float* __restrict__ w1i, const float* __restrict__ w1h,
                            const float* __restrict__ b1i, const float* __restrict__ b1h,
                            const float* __restrict__ w2i, const float* __restrict__ w2h,
                            const float* __restrict__ b2i, const float* __restrict__ b2h) {
    const int blk = blockIdx.x, tid = threadIdx.x;
    if (blk < 512) {
        int o = blk * 256 + tid;
        int i = o >> 5, j = o & 31;
        float s = 0.f;
        for (int p = 0; p < 90; p++) s += spp_w[i * 90 + p] * fw[p * 32 + j];
        g_G[o] = s;
    } else if (blk < 528) {
        int i = (blk - 512) * 256 + tid;
        float s = spp_b[i];
        for (int p = 0; p < 90; p++) s += spp_w[i * 90 + p] * fb[p];
        g_cvec[i] = s;
    } else if (blk == 528) {
        g_b1c[tid] = b1i[tid] + b1h[tid];
        if (tid < 128) g_b2c[tid] = b2i[tid] + b2h[tid];
    } else if (blk == 529) {
        for (int idx = tid; idx < 32768; idx += 256) {
            int g = idx >> 7, k = idx & 127;
            g_Wcat1[idx] = (k < 64) ? w1i[g * 64 + k] : w1h[g * 64 + (k - 64)];
        }
    } else if (blk == 530) {
        for (int idx = tid; idx < 12288; idx += 256) {
            int g = idx / 96, k = idx - g * 96;
            g_Wcat2[idx] = (k < 64) ? w2i[g * 64 + k] : w2h[g * 32 + (k - 64)];
        }
    }
}

// ---------------- GEMM: C = act(A(m,k) * W(n,k)^T + bias), 128x128 tiles ----------------
__global__ void __launch_bounds__(256) gemm128(
        const float* __restrict__ A, int lda,
        const float* __restrict__ W, int ldw,
        const float* __restrict__ bias,
        float* __restrict__ C, int ldc, int K, int do_relu) {
    __shared__ float As[32][132];
    __shared__ float Ws[32][132];
    const int tid = threadIdx.x;
    const int m0 = blockIdx.y * 128, n0 = blockIdx.x * 128;
    const int tx = tid & 15, ty = tid >> 4;
    float acc[8][8];
#pragma unroll
    for (int i = 0; i < 8; i++)
#pragma unroll
        for (int j = 0; j < 8; j++) acc[i][j] = 0.f;
    for (int kc = 0; kc < K; kc += 32) {
#pragma unroll
        for (int i = 0; i < 16; i++) {
            int idx = tid + i * 256;
            int r = idx >> 5, k = idx & 31;
            As[k][r] = (kc + k < K) ? A[(size_t)(m0 + r) * lda + kc + k] : 0.f;
        }
#pragma unroll
        for (int i = 0; i < 16; i++) {
            int idx = tid + i * 256;
            int r = idx >> 5, k = idx & 31;
            Ws[k][r] = (kc + k < K) ? W[(size_t)(n0 + r) * ldw + kc + k] : 0.f;
        }
        __syncthreads();
#pragma unroll
        for (int k = 0; k < 32; k++) {
            float a[8], b[8];
            *(float4*)&a[0] = *(const float4*)&As[k][ty * 8];
            *(float4*)&a[4] = *(const float4*)&As[k][ty * 8 + 4];
            *(float4*)&b[0] = *(const float4*)&Ws[k][tx * 8];
            *(float4*)&b[4] = *(const float4*)&Ws[k][tx * 8 + 4];
#pragma unroll
            for (int i = 0; i < 8; i++)
#pragma unroll
                for (int j = 0; j < 8; j++) acc[i][j] += a[i] * b[j];
        }
        __syncthreads();
    }
#pragma unroll
    for (int i = 0; i < 8; i++) {
        int row = m0 + ty * 8 + i;
#pragma unroll
        for (int j = 0; j < 8; j++) {
            int col = n0 + tx * 8 + j;
            float v = acc[i][j] + bias[col];
            if (do_relu) v = fmaxf(v, 0.f);
            C[(size_t)row * ldc + col] = v;
        }
    }
}

// ---------------- split-K GEMM: part[s][m][n] = sum_{k in split} A[m][k]*W[n][k]; K=4096,N=64 ----------------
__global__ void __launch_bounds__(256) gemm_splitk(const float* __restrict__ A,
                                                   const float* __restrict__ W,
                                                   float* __restrict__ part) {
    __shared__ float As[32][68];
    __shared__ float Ws[32][68];
    const int tid = threadIdx.x;
    const int s = blockIdx.x, m0 = blockIdx.y * 64;
    const int tx = tid & 15, ty = tid >> 4;
    float acc[4][4];
#pragma unroll
    for (int i = 0; i < 4; i++)
#pragma unroll
        for (int j = 0; j < 4; j++) acc[i][j] = 0.f;
    const int kbase = s * 256;
    for (int kc = 0; kc < 256; kc += 32) {
#pragma unroll
        for (int i = 0; i < 8; i++) {
            int idx = tid + i * 256;
            int r = idx >> 5, k = idx & 31;
            As[k][r] = A[(size_t)(m0 + r) * 4096 + kbase + kc + k];
            Ws[k][r] = W[(size_t)r * 4096 + kbase + kc + k];
        }
        __syncthreads();
#pragma unroll
        for (int k = 0; k < 32; k++) {
            float4 a = *(const float4*)&As[k][ty * 4];
            float4 b = *(const float4*)&Ws[k][tx * 4];
            float av[4] = {a.x, a.y, a.z, a.w};
            float bv[4] = {b.x, b.y, b.z, b.w};
#pragma unroll
            for (int i = 0; i < 4; i++)
#pragma unroll
                for (int j = 0; j < 4; j++) acc[i][j] += av[i] * bv[j];
        }
        __syncthreads();
    }
#pragma unroll
    for (int i = 0; i < 4; i++)
#pragma unroll
        for (int j = 0; j < 4; j++)
            part[((size_t)s * NROWS + m0 + ty * 4 + i) * 64 + tx * 4 + j] = acc[i][j];
}

// ---------------- finalize emb = relu(sum parts + b7) ----------------
__global__ void emb_fin(const float* __restrict__ fc7_b) {
    int gid = blockIdx.x * 256 + threadIdx.x;     // 131072
    int row = gid >> 6, j = gid & 63;
    float s = fc7_b[j];
#pragma unroll
    for (int ss = 0; ss < 16; ss++) s += g_part[((size_t)ss * NROWS + row) * 64 + j];
    g_EMB[gid] = fmaxf(s, 0.f);
}

// ---------------- cat1 = [relu(sum parts + b7) | h1] ----------------
__global__ void cat1_build(const float* __restrict__ fc7_b) {
    int gid = blockIdx.x * 256 + threadIdx.x;     // 262144
    int row = gid >> 7, k = gid & 127;
    float v;
    if (k < 64) {
        float s = fc7_b[k];
#pragma unroll
        for (int ss = 0; ss < 16; ss++) s += g_part[((size_t)ss * NROWS + row) * 64 + k];
        v = fmaxf(s, 0.f);
    } else {
        v = g_states[(size_t)row * 192 + (k - 64)];
    }
    g_cat1[gid] = v;
}

// ---------------- sequential LSTM scan, weights in registers ----------------
__global__ void __launch_bounds__(256, 1) scan_kernel(
        const float* __restrict__ w1h, const float* __restrict__ w2i,
        const float* __restrict__ w2h, const float* __restrict__ b2i,
        const float* __restrict__ b2h) {
    __shared__ float h1s[64], c1s[64], h2s[32], c2s[32], act1[256], act2[128];
    const int tid = threadIdx.x;
    const int b = blockIdx.x;
    float w1r[64];
#pragma unroll
    for (int k = 0; k < 64; k++) w1r[k] = w1h[tid * 64 + k];
    float w2ir[64], w2hr[32], bc2 = 0.f;
    if (tid >= 128) {
        int g = tid - 128;
#pragma unroll
        for (int k = 0; k < 64; k++) w2ir[k] = w2i[g * 64 + k];
#pragma unroll
        for (int k = 0; k < 32; k++) w2hr[k] = w2h[g * 32 + k];
        bc2 = b2i[g] + b2h[g];
    }
    if (tid < 64) { h1s[tid] = 0.f; c1s[tid] = 0.f; }
    if (tid < 32) { h2s[tid] = 0.f; c2s[tid] = 0.f; }
    __syncthreads();
    const float* xp = g_XP + (size_t)b * 256 * 256;
    float* st = g_states + (size_t)b * 256 * 192;
    for (int t = 0; t < 256; t++) {
        float acc = xp[t * 256 + tid];
#pragma unroll
        for (int kk = 0; kk < 16; kk++) {
            float4 h = *(const float4*)&h1s[kk * 4];
            acc += w1r[kk * 4] * h.x + w1r[kk * 4 + 1] * h.y
                 + w1r[kk * 4 + 2] * h.z + w1r[kk * 4 + 3] * h.w;
        }
        act1[tid] = ((tid >> 6) == 2) ? tanhf(acc) : sigf(acc);
        __syncthreads();
        if (tid < 64) {
            float c = act1[64 + tid] * c1s[tid] + act1[tid] * act1[128 + tid];
            float h = act1[192 + tid] * tanhf(c);
            c1s[tid] = c; h1s[tid] = h;
            st[t * 192 + tid] = h;
            st[t * 192 + 64 + tid] = c;
        }
        __syncthreads();
        if (tid >= 128) {
            int g = tid - 128;
            float a2 = bc2;
#pragma unroll
            for (int kk = 0; kk < 16; kk++) {
                float4 h = *(const float4*)&h1s[kk * 4];
                a2 += w2ir[kk * 4] * h.x + w2ir[kk * 4 + 1] * h.y
                    + w2ir[kk * 4 + 2] * h.z + w2ir[kk * 4 + 3] * h.w;
            }
#pragma unroll
            for (int kk = 0; kk < 8; kk++) {
                float4 h = *(const float4*)&h2s[kk * 4];
                a2 += w2hr[kk * 4] * h.x + w2hr[kk * 4 + 1] * h.y
                    + w2hr[kk * 4 + 2] * h.z + w2hr[kk * 4 + 3] * h.w;
            }
            act2[g] = ((g >> 5) == 2) ? tanhf(a2) : sigf(a2);
        }
        __syncthreads();
        if (tid < 32) {
            float c = act2[32 + tid] * c2s[tid] + act2[tid] * act2[64 + tid];
            float h = act2[96 + tid] * tanhf(c);
            c2s[tid] = c; h2s[tid] = h;
            st[t * 192 + 128 + tid] = h;
            st[t * 192 + 160 + tid] = c;
        }
        __syncthreads();
    }
}

// ---------------- flstm1 elementwise -> cat2 = [fh1 | h2] ----------------
__global__ void flstm1_kernel() {
    const int row = blockIdx.x, j = threadIdx.x;  // 64 threads
    const float* g1 = g_XP + (size_t)row * 256;
    float i = sigf(g1[j]);
    float f = sigf(g1[64 + j]);
    float gg = tanhf(g1[128 + j]);
    float o = sigf(g1[192 + j]);
    float c1 = g_states[(size_t)row * 192 + 64 + j];
    float cn = f * c1 + i * gg;
    g_cat2[(size_t)row * 96 + j] = o * tanhf(cn);
    if (j < 32) g_cat2[(size_t)row * 96 + 64 + j] = g_states[(size_t)row * 192 + 128 + j];
}

// ---------------- flstm2 + both sigmoid heads ----------------
__global__ void prog_kernel(const float* __restrict__ fc8w, const float* __restrict__ fc8b,
                            float* __restrict__ out) {
    const int row = blockIdx.x, j = threadIdx.x;  // 32 threads
    float w = fc8w[j];
    float h2 = g_states[(size_t)row * 192 + 128 + j];
    float v1 = h2 * w;
    const float* g2 = g_gates2 + (size_t)row * 128;
    float i = sigf(g2[j]);
    float f = sigf(g2[32 + j]);
    float gg = tanhf(g2[64 + j]);
    float o = sigf(g2[96 + j]);
    float c2 = g_states[(size_t)row * 192 + 160 + j];
    float cn = f * c2 + i * gg;
    float fh2 = o * tanhf(cn);
    float v2 = fh2 * w;
#pragma unroll
    for (int off = 16; off > 0; off >>= 1) {
        v1 += __shfl_down_sync(0xffffffffu, v1, off);
        v2 += __shfl_down_sync(0xffffffffu, v2, off);
    }
    if (j == 0) {
        out[row] = sigf(v1 + fc8b[0]);
        out[NROWS + row] = sigf(v2 + fc8b[0]);
    }
}

// ---------------- fpooled = h2 @ F^T + fb ----------------
__global__ void fpool_kernel(const float* __restrict__ fw, const float* __restrict__ fb,
                             float* __restrict__ fpooled) {
    __shared__ float h2sh[32];
    const int row = blockIdx.x, tid = threadIdx.x;  // 96 threads
    if (tid < 32) h2sh[tid] = g_states[(size_t)row * 192 + 128 + tid];
    __syncthreads();
    if (tid < 90) {
        float s = fb[tid];
#pragma unroll
        for (int k = 0; k < 32; k++) s += h2sh[k] * fw[tid * 32 + k];
        fpooled[(size_t)row * 90 + tid] = s;
    }
}

// ---------------- host ----------------
extern "C" void kernel_launch(void* const* d_in, const int* in_sizes, int n_in,
                              void* d_out, int out_size) {
    const float* frames = (const float*)d_in[0];
    const float* spp_w  = (const float*)d_in[1];
    const float* spp_b  = (const float*)d_in[2];
    const float* fc7_w  = (const float*)d_in[3];
    const float* fc7_b  = (const float*)d_in[4];
    const float* w1i    = (const float*)d_in[5];
    const float* w1h    = (const float*)d_in[6];
    const float* b1i    = (const float*)d_in[7];
    const float* b1h    = (const float*)d_in[8];
    const float* w2i    = (const float*)d_in[9];
    const float* w2h    = (const float*)d_in[10];
    const float* b2i    = (const float*)d_in[11];
    const float* b2h    = (const float*)d_in[12];
    const float* fw     = (const float*)d_in[13];
    const float* fb     = (const float*)d_in[14];
    const float* fc8w   = (const float*)d_in[15];
    const float* fc8b   = (const float*)d_in[16];
    float* out = (float*)d_out;

    float *H, *PART, *EMB, *XP, *ST, *G, *CV, *C1, *C2, *G2, *WC1, *WC2, *B1C, *B2C;
    cudaGetSymbolAddress((void**)&H, g_H);
    cudaGetSymbolAddress((void**)&PART, g_part);
    cudaGetSymbolAddress((void**)&EMB, g_EMB);
    cudaGetSymbolAddress((void**)&XP, g_XP);
    cudaGetSymbolAddress((void**)&ST, g_states);
    cudaGetSymbolAddress((void**)&G, g_G);
    cudaGetSymbolAddress((void**)&CV, g_cvec);
    cudaGetSymbolAddress((void**)&C1, g_cat1);
    cudaGetSymbolAddress((void**)&C2, g_cat2);
    cudaGetSymbolAddress((void**)&G2, g_gates2);
    cudaGetSymbolAddress((void**)&WC1, g_Wcat1);
    cudaGetSymbolAddress((void**)&WC2, g_Wcat2);
    cudaGetSymbolAddress((void**)&B1C, g_b1c);
    cudaGetSymbolAddress((void**)&B2C, g_b2c);

    float* pooled  = out + 2 * NROWS;
    float* fpooled = out + 2 * NROWS + NROWS * 90;

    spp_kernel<<<6144, 160>>>(frames, pooled);
    prep_kernel<<<531, 256>>>(spp_w, spp_b, fw, fb, w1i, w1h, b1i, b1h, w2i, w2h, b2i, b2h);
    // E1 = relu(pooled @ spp_w^T + spp_b)
    gemm128<<<dim3(32, 16), 256>>>(pooled, 90, spp_w, 90, spp_b, H, 4096, 90, 1);
    // emb partials = E1 @ fc7_w^T
    gemm_splitk<<<dim3(16, 32), 256>>>(H, fc7_w, PART);
    emb_fin<<<512, 256>>>(fc7_b);
    // XP = emb @ w1i^T + (b1i+b1h)
    gemm128<<<dim3(2, 16), 256>>>(EMB, 64, w1i, 64, B1C, XP, 256, 64, 0);
    scan_kernel<<<8, 256>>>(w1h, w2i, w2h, b2i, b2h);
    // fe_pre = relu(h2 @ G^T + cvec)
    gemm128<<<dim3(32, 16), 256>>>(ST + 128, 192, G, 32, CV, H, 4096, 32, 1);
    gemm_splitk<<<dim3(16, 32), 256>>>(H, fc7_w, PART);
    cat1_build<<<1024, 256>>>(fc7_b);
    // gates1f = cat1 @ Wcat1^T + b1c
    gemm128<<<dim3(2, 16), 256>>>(C1, 128, WC1, 128, B1C, XP, 256, 128, 0);
    flstm1_kernel<<<2048, 64>>>();
    // gates2f = cat2 @ Wcat2^T + b2c
    gemm128<<<dim3(1, 16), 256>>>(C2, 96, WC2, 96, B2C, G2, 128, 96, 0);
    prog_kernel<<<2048, 32>>>(fc8w, fc8b, out);
    fpool_kernel<<<2048, 96>>>(fw, fb, fpooled);
}

// round 3
// speedup vs baseline: 1.0908x; 1.0908x over previous
#include <cuda_runtime.h>
#include <cuda_bf16.h>
#include <math.h>

#define NROWS 2048
#define EMBED 4096
#define SPLITS 8

// ---------------- scratch ----------------
__device__ float g_H[NROWS * EMBED];
__device__ float g_part[SPLITS * NROWS * 64];
__device__ float g_EMB[NROWS * 64];
__device__ float g_XP[NROWS * 256];
__device__ float g_states[NROWS * 192];   // per row: h1[64] c1[64] h2[32] c2[32]
__device__ float g_G[EMBED * 32];
__device__ float g_cvec[EMBED];
__device__ float g_cat1[NROWS * 128];
__device__ float g_Wcat1[256 * 128];
__device__ float g_Wcat2[128 * 96];
__device__ float g_b1c[256];
__device__ float g_b2c[128];

__device__ __forceinline__ float sig_f(float x) {
    return __fdividef(1.0f, 1.0f + __expf(-x));
}
__device__ __forceinline__ float tanh_f(float x) {
    return __fdividef(2.0f, 1.0f + __expf(-2.0f * x)) - 1.0f;
}

// ---------------- SPP ----------------
__global__ void spp_kernel(const float* __restrict__ frames, float* __restrict__ pooled) {
    __shared__ float tmax[144];
    const int nc = blockIdx.x;
    const int n = nc / 3, c = nc % 3;
    const float* img = frames + (size_t)nc * 9216;
    const int tid = threadIdx.x;
    if (tid < 144) {
        const int ti = tid / 12, tj = tid % 12;
        const float* p = img + ti * 8 * 96 + tj * 8;
        float m = -3.402823466e38f;
#pragma unroll
        for (int r = 0; r < 8; r++) {
            float4 v0 = *(const float4*)(p + r * 96);
            float4 v1 = *(const float4*)(p + r * 96 + 4);
            m = fmaxf(m, fmaxf(fmaxf(v0.x, v0.y), fmaxf(v0.z, v0.w)));
            m = fmaxf(m, fmaxf(fmaxf(v1.x, v1.y), fmaxf(v1.z, v1.w)));
        }
        tmax[tid] = m;
    }
    __syncthreads();
    float* orow = pooled + (size_t)n * 90;
    if (tid < 16) {
        int i = tid / 4, j = tid % 4;
        float m = -3.402823466e38f;
        for (int a = 0; a < 3; a++) for (int b = 0; b < 3; b++)
            m = fmaxf(m, tmax[(i * 3 + a) * 12 + (j * 3 + b)]);
        orow[c * 16 + i * 4 + j] = m;
    } else if (tid < 25) {
        int q = tid - 16, i = q / 3, j = q % 3;
        float m = -3.402823466e38f;
        for (int a = 0; a < 4; a++) for (int b = 0; b < 4; b++)
            m = fmaxf(m, tmax[(i * 4 + a) * 12 + (j * 4 + b)]);
        orow[48 + c * 9 + i * 3 + j] = m;
    } else if (tid < 29) {
        int q = tid - 25, i = q / 2, j = q % 2;
        float m = -3.402823466e38f;
        for (int a = 0; a < 6; a++) for (int b = 0; b < 6; b++)
            m = fmaxf(m, tmax[(i * 6 + a) * 12 + (j * 6 + b)]);
        orow[75 + c * 4 + i * 2 + j] = m;
    } else if (tid == 29) {
        float m = -3.402823466e38f;
        for (int a = 0; a < 144; a++) m = fmaxf(m, tmax[a]);
        orow[87 + c] = m;
    }
}

// ---------------- prep ----------------
__global__ void prep_kernel(const float* __restrict__ spp_w, const float* __restrict__ spp_b,
                            const float* __restrict__ fw, const float* __restrict__ fb,
                            const float* __restrict__ w1i, const float* __restrict__ w1h,
                            const float* __restrict__ b1i, const float* __restrict__ b1h,
                            const float* __restrict__ w2i, const float* __restrict__ w2h,
                            const float* __restrict__ b2i, const float* __restrict__ b2h) {
    const int blk = blockIdx.x, tid = threadIdx.x;
    if (blk < 512) {
        int o = blk * 256 + tid;
        int i = o >> 5, j = o & 31;
        float s = 0.f;
        for (int p = 0; p < 90; p++) s += spp_w[i * 90 + p] * fw[p * 32 + j];
        g_G[o] = s;
    } else if (blk < 528) {
        int i = (blk - 512) * 256 + tid;
        float s = spp_b[i];
        for (int p = 0; p < 90; p++) s += spp_w[i * 90 + p] * fb[p];
        g_cvec[i] = s;
    } else if (blk == 528) {
        g_b1c[tid] = b1i[tid] + b1h[tid];
        if (tid < 128) g_b2c[tid] = b2i[tid] + b2h[tid];
    } else if (blk == 529) {
        for (int idx = tid; idx < 32768; idx += 256) {
            int g = idx >> 7, k = idx & 127;
            g_Wcat1[idx] = (k < 64) ? w1i[g * 64 + k] : w1h[g * 64 + (k - 64)];
        }
    } else if (blk == 530) {
        for (int idx = tid; idx < 12288; idx += 256) {
            int g = idx / 96, k = idx - g * 96;
            g_Wcat2[idx] = (k < 64) ? w2i[g * 64 + k] : w2h[g * 32 + (k - 64)];
        }
    }
}

// ---------------- GEMM: C = act(A(m,k) * W(n,k)^T + bias), 128x128 tiles ----------------
__global__ void __launch_bounds__(256) gemm128(
        const float* __restrict__ A, int lda,
        const float* __restrict__ W, int ldw,
        const float* __restrict__ bias,
        float* __restrict__ C, int ldc, int K, int do_relu) {
    __shared__ float As[32][132];
    __shared__ float Ws[32][132];
    const int tid = threadIdx.x;
    const int m0 = blockIdx.y * 128, n0 = blockIdx.x * 128;
    const int tx = tid & 15, ty = tid >> 4;
    float acc[8][8];
#pragma unroll
    for (int i = 0; i < 8; i++)
#pragma unroll
        for (int j = 0; j < 8; j++) acc[i][j] = 0.f;
    for (int kc = 0; kc < K; kc += 32) {
#pragma unroll
        for (int i = 0; i < 16; i++) {
            int idx = tid + i * 256;
            int r = idx >> 5, k = idx & 31;
            As[k][r] = (kc + k < K) ? A[(size_t)(m0 + r) * lda + kc + k] : 0.f;
        }
#pragma unroll
        for (int i = 0; i < 16; i++) {
            int idx = tid + i * 256;
            int r = idx >> 5, k = idx & 31;
            Ws[k][r] = (kc + k < K) ? W[(size_t)(n0 + r) * ldw + kc + k] : 0.f;
        }
        __syncthreads();
#pragma unroll
        for (int k = 0; k < 32; k++) {
            float a[8], b[8];
            *(float4*)&a[0] = *(const float4*)&As[k][ty * 8];
            *(float4*)&a[4] = *(const float4*)&As[k][ty * 8 + 4];
            *(float4*)&b[0] = *(const float4*)&Ws[k][tx * 8];
            *(float4*)&b[4] = *(const float4*)&Ws[k][tx * 8 + 4];
#pragma unroll
            for (int i = 0; i < 8; i++)
#pragma unroll
                for (int j = 0; j < 8; j++) acc[i][j] += a[i] * b[j];
        }
        __syncthreads();
    }
#pragma unroll
    for (int i = 0; i < 8; i++) {
        int row = m0 + ty * 8 + i;
#pragma unroll
        for (int j = 0; j < 8; j++) {
            int col = n0 + tx * 8 + j;
            float v = acc[i][j] + bias[col];
            if (do_relu) v = fmaxf(v, 0.f);
            C[(size_t)row * ldc + col] = v;
        }
    }
}

// ---------------- split-K GEMM: K=4096, N=64; 128x64 tiles, 8x4 microtile, reg prefetch ----
__global__ void __launch_bounds__(256) gemm_splitk(const float* __restrict__ A,
                                                   const float* __restrict__ W,
                                                   float* __restrict__ part) {
    __shared__ float As[32][132];
    __shared__ float Ws[32][68];
    const int tid = threadIdx.x;
    const int s = blockIdx.x, m0 = blockIdx.y * 128;
    const int tx = tid & 15, ty = tid >> 4;   // 16 col-groups x 16 row-groups
    float acc[8][4];
#pragma unroll
    for (int i = 0; i < 8; i++)
#pragma unroll
        for (int j = 0; j < 4; j++) acc[i][j] = 0.f;
    const int kbase = s * 512;
    const float* Ablk = A + (size_t)m0 * 4096 + kbase;
    const float* Wblk = W + kbase;
    float pa[16], pw[8];
#pragma unroll
    for (int i = 0; i < 16; i++) {
        int idx = tid + i * 256;
        pa[i] = Ablk[(size_t)(idx >> 5) * 4096 + (idx & 31)];
    }
#pragma unroll
    for (int i = 0; i < 8; i++) {
        int idx = tid + i * 256;
        pw[i] = Wblk[(size_t)(idx >> 5) * 4096 + (idx & 31)];
    }
#pragma unroll 1
    for (int kc = 0; kc < 512; kc += 32) {
#pragma unroll
        for (int i = 0; i < 16; i++) {
            int idx = tid + i * 256;
            As[idx & 31][idx >> 5] = pa[i];
        }
#pragma unroll
        for (int i = 0; i < 8; i++) {
            int idx = tid + i * 256;
            Ws[idx & 31][idx >> 5] = pw[i];
        }
        __syncthreads();
        if (kc + 32 < 512) {
#pragma unroll
            for (int i = 0; i < 16; i++) {
                int idx = tid + i * 256;
                pa[i] = Ablk[(size_t)(idx >> 5) * 4096 + kc + 32 + (idx & 31)];
            }
#pragma unroll
            for (int i = 0; i < 8; i++) {
                int idx = tid + i * 256;
                pw[i] = Wblk[(size_t)(idx >> 5) * 4096 + kc + 32 + (idx & 31)];
            }
        }
#pragma unroll
        for (int k = 0; k < 32; k++) {
            float a[8], b[4];
            *(float4*)&a[0] = *(const float4*)&As[k][ty * 8];
            *(float4*)&a[4] = *(const float4*)&As[k][ty * 8 + 4];
            *(float4*)&b[0] = *(const float4*)&Ws[k][tx * 4];
#pragma unroll
            for (int i = 0; i < 8; i++)
#pragma unroll
                for (int j = 0; j < 4; j++) acc[i][j] += a[i] * b[j];
        }
        __syncthreads();
    }
#pragma unroll
    for (int i = 0; i < 8; i++)
#pragma unroll
        for (int j = 0; j < 4; j++)
            part[((size_t)s * NROWS + m0 + ty * 8 + i) * 64 + tx * 4 + j] = acc[i][j];
}

// ---------------- finalize emb = relu(sum parts + b7) ----------------
__global__ void emb_fin(const float* __restrict__ fc7_b) {
    int gid = blockIdx.x * 256 + threadIdx.x;     // 131072
    int row = gid >> 6, j = gid & 63;
    float s = fc7_b[j];
#pragma unroll
    for (int ss = 0; ss < SPLITS; ss++) s += g_part[((size_t)ss * NROWS + row) * 64 + j];
    g_EMB[gid] = fmaxf(s, 0.f);
}

// ---------------- cat1 = [relu(sum parts + b7) | h1] ----------------
__global__ void cat1_build(const float* __restrict__ fc7_b) {
    int gid = blockIdx.x * 256 + threadIdx.x;     // 262144
    int row = gid >> 7, k = gid & 127;
    float v;
    if (k < 64) {
        float s = fc7_b[k];
#pragma unroll
        for (int ss = 0; ss < SPLITS; ss++) s += g_part[((size_t)ss * NROWS + row) * 64 + k];
        v = fmaxf(s, 0.f);
    } else {
        v = g_states[(size_t)row * 192 + (k - 64)];
    }
    g_cat1[gid] = v;
}

// ---------------- two-phase sequential LSTM scan ----------------
// phase 1: lstm1 over all t (2 syncs/step), h1 history kept in smem.
// phase 2: lstm2 over all t reading h1 history from smem (2 syncs/step).
__global__ void __launch_bounds__(256, 1) scan_kernel(
        const float* __restrict__ w1h, const float* __restrict__ w2i,
        const float* __restrict__ w2h, const float* __restrict__ b2i,
        const float* __restrict__ b2h) {
    extern __shared__ float sm[];
    float* h1hist = sm;                 // 256*64
    float* h1cur  = sm + 16384;         // 64
    float* c1cur  = h1cur + 64;         // 64
    float* act    = c1cur + 64;         // 256
    float* h2cur  = act + 256;          // 32
    float* c2cur  = h2cur + 32;         // 32
    const int tid = threadIdx.x;
    const int b = blockIdx.x;
    const float* xp = g_XP + (size_t)b * 65536;
    float* st = g_states + (size_t)b * 49152;

    // ---- phase 1 ----
    {
        float w1r[64];
#pragma unroll
        for (int k = 0; k < 64; k++) w1r[k] = w1h[tid * 64 + k];
        if (tid < 64) { h1cur[tid] = 0.f; c1cur[tid] = 0.f; }
        if (tid < 32) { h2cur[tid] = 0.f; c2cur[tid] = 0.f; }
        __syncthreads();
        float xnext = xp[tid];
        const bool is_tanh = (tid >= 128 && tid < 192);
        for (int t = 0; t < 256; t++) {
            float a0 = xnext, a1 = 0.f, a2 = 0.f, a3 = 0.f;
            if (t < 255) xnext = xp[(t + 1) * 256 + tid];
#pragma unroll
            for (int kk = 0; kk < 16; kk++) {
                float4 h = *(const float4*)&h1cur[kk * 4];
                a0 += w1r[kk * 4 + 0] * h.x;
                a1 += w1r[kk * 4 + 1] * h.y;
                a2 += w1r[kk * 4 + 2] * h.z;
                a3 += w1r[kk * 4 + 3] * h.w;
            }
            float g = (a0 + a1) + (a2 + a3);
            act[tid] = is_tanh ? tanh_f(g) : sig_f(g);
            __syncthreads();
            if (tid < 64) {
                float c = act[64 + tid] * c1cur[tid] + act[tid] * act[128 + tid];
                float h = act[192 + tid] * tanh_f(c);
                c1cur[tid] = c; h1cur[tid] = h;
                h1hist[t * 64 + tid] = h;
                st[t * 192 + tid] = h;
                st[t * 192 + 64 + tid] = c;
            }
            __syncthreads();
        }
    }
    // ---- phase 2 ----
    {
        float w2ir[64], w2hr[32], bc2 = 0.f;
        if (tid < 128) {
#pragma unroll
            for (int k = 0; k < 64; k++) w2ir[k] = w2i[tid * 64 + k];
#pragma unroll
            for (int k = 0; k < 32; k++) w2hr[k] = w2h[tid * 32 + k];
            bc2 = b2i[tid] + b2h[tid];
        }
        const bool is_tanh2 = (tid >= 64 && tid < 96);
        for (int t = 0; t < 256; t++) {
            if (tid < 128) {
                float a0 = bc2, a1 = 0.f, a2 = 0.f, a3 = 0.f;
#pragma unroll
                for (int kk = 0; kk < 16; kk++) {
                    float4 h = *(const float4*)&h1hist[t * 64 + kk * 4];
                    a0 += w2ir[kk * 4 + 0] * h.x;
                    a1 += w2ir[kk * 4 + 1] * h.y;
                    a2 += w2ir[kk * 4 + 2] * h.z;
                    a3 += w2ir[kk * 4 + 3] * h.w;
                }
#pragma unroll
                for (int kk = 0; kk < 8; kk++) {
                    float4 h = *(const float4*)&h2cur[kk * 4];
                    a0 += w2hr[kk * 4 + 0] * h.x;
                    a1 += w2hr[kk * 4 + 1] * h.y;
                    a2 += w2hr[kk * 4 + 2] * h.z;
                    a3 += w2hr[kk * 4 + 3] * h.w;
                }
                float g = (a0 + a1) + (a2 + a3);
                act[tid] = is_tanh2 ? tanh_f(g) : sig_f(g);
            }
            __syncthreads();
            if (tid < 32) {
                float c = act[32 + tid] * c2cur[tid] + act[tid] * act[64 + tid];
                float h = act[96 + tid] * tanh_f(c);
                c2cur[tid] = c; h2cur[tid] = h;
                st[t * 192 + 128 + tid] = h;
                st[t * 192 + 160 + tid] = c;
            }
            __syncthreads();
        }
    }
}

// ---------------- fused tail: flstm1 + gates2f + heads + fpool ----------------
__global__ void __launch_bounds__(128) tail_kernel(
        const float* __restrict__ fc8w, const float* __restrict__ fc8b,
        const float* __restrict__ fw, const float* __restrict__ fb,
        float* __restrict__ out, float* __restrict__ fpooled) {
    __shared__ float fh1[64], h2s[32], c2s[32], gs[128];
    const int tid = threadIdx.x;
    float wcat[96];
#pragma unroll
    for (int k = 0; k < 96; k++) wcat[k] = g_Wcat2[tid * 96 + k];
    const float b2 = g_b2c[tid];
    const int po = tid - 32;
    float fwr[32];
    if (po >= 0 && po < 90) {
#pragma unroll
        for (int k = 0; k < 32; k++) fwr[k] = fw[po * 32 + k];
    }
    const float w8 = (tid < 32) ? fc8w[tid] : 0.f;
    const float b8 = fc8b[0];
    const bool is_tanh2 = (tid >= 64 && tid < 96);

    for (int r = 0; r < 4; r++) {
        const int row = blockIdx.x * 4 + r;
        const float* xpf = g_XP + (size_t)row * 256;
        const float* st = g_states + (size_t)row * 192;
        if (tid < 64) {
            float i = sig_f(xpf[tid]);
            float f = sig_f(xpf[64 + tid]);
            float gg = tanh_f(xpf[128 + tid]);
            float o = sig_f(xpf[192 + tid]);
            float cn = f * st[64 + tid] + i * gg;
            fh1[tid] = o * tanh_f(cn);
        } else if (tid < 96) {
            h2s[tid - 64] = st[128 + (tid - 64)];
        } else {
            c2s[tid - 96] = st[160 + (tid - 96)];
        }
        __syncthreads();
        float a = b2;
#pragma unroll
        for (int k = 0; k < 64; k++) a += wcat[k] * fh1[k];
#pragma unroll
        for (int k = 0; k < 32; k++) a += wcat[64 + k] * h2s[k];
        gs[tid] = is_tanh2 ? tanh_f(a) : sig_f(a);
        __syncthreads();
        if (tid < 32) {
            float cn = gs[32 + tid] * c2s[tid] + gs[tid] * gs[64 + tid];
            float fh2 = gs[96 + tid] * tanh_f(cn);
            float v1 = h2s[tid] * w8;
            float v2 = fh2 * w8;
#pragma unroll
            for (int off = 16; off > 0; off >>= 1) {
                v1 += __shfl_down_sync(0xffffffffu, v1, off);
                v2 += __shfl_down_sync(0xffffffffu, v2, off);
            }
            if (tid == 0) {
                out[row] = sig_f(v1 + b8);
                out[NROWS + row] = sig_f(v2 + b8);
            }
        } else if (po < 90) {
            float s2 = fb[po];
#pragma unroll
            for (int k = 0; k < 32; k++) s2 += fwr[k] * h2s[k];
            fpooled[(size_t)row * 90 + po] = s2;
        }
        __syncthreads();
    }
}

// ---------------- host ----------------
extern "C" void kernel_launch(void* const* d_in, const int* in_sizes, int n_in,
                              void* d_out, int out_size) {
    const float* frames = (const float*)d_in[0];
    const float* spp_w  = (const float*)d_in[1];
    const float* spp_b  = (const float*)d_in[2];
    const float* fc7_w  = (const float*)d_in[3];
    const float* fc7_b  = (const float*)d_in[4];
    const float* w1i    = (const float*)d_in[5];
    const float* w1h    = (const float*)d_in[6];
    const float* b1i    = (const float*)d_in[7];
    const float* b1h    = (const float*)d_in[8];
    const float* w2i    = (const float*)d_in[9];
    const float* w2h    = (const float*)d_in[10];
    const float* b2i    = (const float*)d_in[11];
    const float* b2h    = (const float*)d_in[12];
    const float* fw     = (const float*)d_in[13];
    const float* fb     = (const float*)d_in[14];
    const float* fc8w   = (const float*)d_in[15];
    const float* fc8b   = (const float*)d_in[16];
    float* out = (float*)d_out;

    float *H, *PART, *EMB, *XP, *ST, *G, *CV, *C1, *WC1, *B1C, *B2C;
    cudaGetSymbolAddress((void**)&H, g_H);
    cudaGetSymbolAddress((void**)&PART, g_part);
    cudaGetSymbolAddress((void**)&EMB, g_EMB);
    cudaGetSymbolAddress((void**)&XP, g_XP);
    cudaGetSymbolAddress((void**)&ST, g_states);
    cudaGetSymbolAddress((void**)&G, g_G);
    cudaGetSymbolAddress((void**)&CV, g_cvec);
    cudaGetSymbolAddress((void**)&C1, g_cat1);
    cudaGetSymbolAddress((void**)&WC1, g_Wcat1);
    cudaGetSymbolAddress((void**)&B1C, g_b1c);
    cudaGetSymbolAddress((void**)&B2C, g_b2c);

    const int scan_smem = (16384 + 64 + 64 + 256 + 32 + 32) * 4;
    cudaFuncSetAttribute(scan_kernel, cudaFuncAttributeMaxDynamicSharedMemorySize, scan_smem);

    float* pooled  = out + 2 * NROWS;
    float* fpooled = out + 2 * NROWS + NROWS * 90;

    spp_kernel<<<6144, 160>>>(frames, pooled);
    prep_kernel<<<531, 256>>>(spp_w, spp_b, fw, fb, w1i, w1h, b1i, b1h, w2i, w2h, b2i, b2h);
    // E1 = relu(pooled @ spp_w^T + spp_b)
    gemm128<<<dim3(32, 16), 256>>>(pooled, 90, spp_w, 90, spp_b, H, 4096, 90, 1);
    // emb partials = E1 @ fc7_w^T
    gemm_splitk<<<dim3(SPLITS, 16), 256>>>(H, fc7_w, PART);
    emb_fin<<<512, 256>>>(fc7_b);
    // XP = emb @ w1i^T + (b1i+b1h)
    gemm128<<<dim3(2, 16), 256>>>(EMB, 64, w1i, 64, B1C, XP, 256, 64, 0);
    scan_kernel<<<8, 256, scan_smem>>>(w1h, w2i, w2h, b2i, b2h);
    // fe_pre = relu(h2 @ G^T + cvec)
    gemm128<<<dim3(32, 16), 256>>>(ST + 128, 192, G, 32, CV, H, 4096, 32, 1);
    gemm_splitk<<<dim3(SPLITS, 16), 256>>>(H, fc7_w, PART);
    cat1_build<<<1024, 256>>>(fc7_b);
    // gates1f = cat1 @ Wcat1^T + b1c  (into XP)
    gemm128<<<dim3(2, 16), 256>>>(C1, 128, WC1, 128, B1C, XP, 256, 128, 0);
    tail_kernel<<<512, 128>>>(fc8w, fc8b, fw, fb, out, fpooled);
}

// round 4
// speedup vs baseline: 1.2744x; 1.1683x over previous
#include <cuda_runtime.h>
#include <cuda_bf16.h>
#include <math.h>

#define NROWS 2048
#define EMBED 4096
#define SPLITS 16

typedef unsigned long long ull;

__device__ __forceinline__ void ffma2(ull& d, ull a, ull b) {
    asm("fma.rn.f32x2 %0, %1, %2, %3;" : "=l"(d) : "l"(a), "l"(b), "l"(d));
}
__device__ __forceinline__ ull pack2f(float x, float y) {
    ull r; asm("mov.b64 %0, {%1, %2};" : "=l"(r) : "f"(x), "f"(y)); return r;
}
__device__ __forceinline__ float2 unpack2f(ull v) {
    float2 f; asm("mov.b64 {%0, %1}, %2;" : "=f"(f.x), "=f"(f.y) : "l"(v)); return f;
}

// ---------------- scratch ----------------
__device__ float g_part[SPLITS * NROWS * 64];
__device__ float g_XP[NROWS * 256];
__device__ float g_states[NROWS * 192];   // per row: h1[64] c1[64] h2[32] c2[32]
__device__ float g_G[EMBED * 32];
__device__ float g_cvec[EMBED];
__device__ float g_Wcat2[128 * 96];
__device__ float g_b1c[256];
__device__ float g_b2c[128];

__device__ __forceinline__ float sig_f(float x) {
    return __fdividef(1.0f, 1.0f + __expf(-x));
}
__device__ __forceinline__ float tanh_f(float x) {
    return __fdividef(2.0f, 1.0f + __expf(-2.0f * x)) - 1.0f;
}

// ---------------- SPP ----------------
__global__ void spp_kernel(const float* __restrict__ frames, float* __restrict__ pooled) {
    __shared__ float tmax[144];
    const int nc = blockIdx.x;
    const int n = nc / 3, c = nc % 3;
    const float* img = frames + (size_t)nc * 9216;
    const int tid = threadIdx.x;
    if (tid < 144) {
        const int ti = tid / 12, tj = tid % 12;
        const float* p = img + ti * 8 * 96 + tj * 8;
        float m = -3.402823466e38f;
#pragma unroll
        for (int r = 0; r < 8; r++) {
            float4 v0 = *(const float4*)(p + r * 96);
            float4 v1 = *(const float4*)(p + r * 96 + 4);
            m = fmaxf(m, fmaxf(fmaxf(v0.x, v0.y), fmaxf(v0.z, v0.w)));
            m = fmaxf(m, fmaxf(fmaxf(v1.x, v1.y), fmaxf(v1.z, v1.w)));
        }
        tmax[tid] = m;
    }
    __syncthreads();
    float* orow = pooled + (size_t)n * 90;
    if (tid < 16) {
        int i = tid / 4, j = tid % 4;
        float m = -3.402823466e38f;
        for (int a = 0; a < 3; a++) for (int b = 0; b < 3; b++)
            m = fmaxf(m, tmax[(i * 3 + a) * 12 + (j * 3 + b)]);
        orow[c * 16 + i * 4 + j] = m;
    } else if (tid < 25) {
        int q = tid - 16, i = q / 3, j = q % 3;
        float m = -3.402823466e38f;
        for (int a = 0; a < 4; a++) for (int b = 0; b < 4; b++)
            m = fmaxf(m, tmax[(i * 4 + a) * 12 + (j * 4 + b)]);
        orow[48 + c * 9 + i * 3 + j] = m;
    } else if (tid < 29) {
        int q = tid - 25, i = q / 2, j = q % 2;
        float m = -3.402823466e38f;
        for (int a = 0; a < 6; a++) for (int b = 0; b < 6; b++)
            m = fmaxf(m, tmax[(i * 6 + a) * 12 + (j * 6 + b)]);
        orow[75 + c * 4 + i * 2 + j] = m;
    } else if (tid == 29) {
        float m = -3.402823466e38f;
        for (int a = 0; a < 144; a++) m = fmaxf(m, tmax[a]);
        orow[87 + c] = m;
    }
}

// ---------------- prep: G = spp_w@fw, cvec, combined biases, Wcat2 ----------------
__global__ void prep_kernel(const float* __restrict__ spp_w, const float* __restrict__ spp_b,
                            const float* __restrict__ fw, const float* __restrict__ fb,
                            const float* __restrict__ b1i, const float* __restrict__ b1h,
                            const float* __restrict__ w2i, const float* __restrict__ w2h,
                            const float* __restrict__ b2i, const float* __restrict__ b2h) {
    const int blk = blockIdx.x, tid = threadIdx.x;
    if (blk < 512) {
        int o = blk * 256 + tid;
        int i = o >> 5, j = o & 31;
        float s = 0.f;
        for (int p = 0; p < 90; p++) s += spp_w[i * 90 + p] * fw[p * 32 + j];
        g_G[o] = s;
    } else if (blk < 528) {
        int i = (blk - 512) * 256 + tid;
        float s = spp_b[i];
        for (int p = 0; p < 90; p++) s += spp_w[i * 90 + p] * fb[p];
        g_cvec[i] = s;
    } else if (blk == 528) {
        g_b1c[tid] = b1i[tid] + b1h[tid];
        if (tid < 128) g_b2c[tid] = b2i[tid] + b2h[tid];
    } else if (blk == 529) {
        for (int idx = tid; idx < 12288; idx += 256) {
            int g = idx / 96, k = idx - g * 96;
            g_Wcat2[idx] = (k < 64) ? w2i[g * 64 + k] : w2h[g * 32 + (k - 64)];
        }
    }
}

// ---------------- fused two-layer MLP with split-K over the 4096 hidden dim ----------------
// part[s][row][n] = sum_{c in split s} relu(A[row]·W1[c] + b1[c]) * fc7[n][c]
// grid (16 splits, 16 row-tiles of 128), 256 threads.
template<int KA>
__global__ void __launch_bounds__(256) fused_mlp(
        const float* __restrict__ A, int lda,
        const float* __restrict__ W1, const float* __restrict__ b1,
        const float* __restrict__ fc7, float* __restrict__ part) {
    constexpr int KAP = KA + 2;
    constexpr int WS  = (KA == 90) ? 90 : 34;   // 2-way-conflict-safe stride
    extern __shared__ float sm[];
    float* A2 = sm;                       // [128][KAP]
    float* W2 = A2 + 128 * KAP;           // [32][WS]
    float* F2 = W2 + 32 * WS;             // [64][36] swizzled
    float* Es = F2 + 64 * 36;             // [128][40] swizzled
    const int tid = threadIdx.x;
    const int s = blockIdx.x, m0 = blockIdx.y * 128;
    for (int idx = tid; idx < 128 * KA; idx += 256) {
        int r = idx / KA, p = idx - r * KA;
        A2[r * KAP + p] = A[(size_t)(m0 + r) * lda + p];
    }
    ull acc2[8][4];
#pragma unroll
    for (int i = 0; i < 8; i++)
#pragma unroll
        for (int j = 0; j < 4; j++) acc2[i][j] = 0ull;
    const int kbase = s * 256;
    const int txE = tid & 7, tyE = tid >> 3;
    const int txM = tid & 15, tyM = tid >> 4;
    const int eswM = 4 * (tyM & 7);
    const int fswM = 4 * (txM & 7);

    for (int kc = 0; kc < 256; kc += 32) {
        const int cg0 = kbase + kc;
        __syncthreads();
        for (int idx = tid; idx < 32 * KA; idx += 256) {
            int c = idx / KA, p = idx - c * KA;
            W2[c * WS + p] = W1[(size_t)(cg0 + c) * KA + p];
        }
        for (int idx = tid; idx < 64 * 32; idx += 256) {
            int n = idx >> 5, kk = idx & 31;
            F2[n * 36 + (kk ^ (4 * ((n >> 2) & 7)))] = fc7[(size_t)n * 4096 + cg0 + kk];
        }
        __syncthreads();
        // ---- E chunk: rows tyE*4.., cols txE*4.. (k-pair packed dot) ----
        ull e2[4][4];
#pragma unroll
        for (int i = 0; i < 4; i++)
#pragma unroll
            for (int j = 0; j < 4; j++) e2[i][j] = 0ull;
        for (int p = 0; p < KA; p += 2) {
            ull a0 = *(const ull*)&A2[(tyE * 4 + 0) * KAP + p];
            ull a1 = *(const ull*)&A2[(tyE * 4 + 1) * KAP + p];
            ull a2 = *(const ull*)&A2[(tyE * 4 + 2) * KAP + p];
            ull a3 = *(const ull*)&A2[(tyE * 4 + 3) * KAP + p];
            ull w0 = *(const ull*)&W2[(txE * 4 + 0) * WS + p];
            ull w1 = *(const ull*)&W2[(txE * 4 + 1) * WS + p];
            ull w2 = *(const ull*)&W2[(txE * 4 + 2) * WS + p];
            ull w3 = *(const ull*)&W2[(txE * 4 + 3) * WS + p];
            ffma2(e2[0][0], a0, w0); ffma2(e2[0][1], a0, w1);
            ffma2(e2[0][2], a0, w2); ffma2(e2[0][3], a0, w3);
            ffma2(e2[1][0], a1, w0); ffma2(e2[1][1], a1, w1);
            ffma2(e2[1][2], a1, w2); ffma2(e2[1][3], a1, w3);
            ffma2(e2[2][0], a2, w0); ffma2(e2[2][1], a2, w1);
            ffma2(e2[2][2], a2, w2); ffma2(e2[2][3], a2, w3);
            ffma2(e2[3][0], a3, w0); ffma2(e2[3][1], a3, w1);
            ffma2(e2[3][2], a3, w2); ffma2(e2[3][3], a3, w3);
        }
#pragma unroll
        for (int i = 0; i < 4; i++) {
            int r = tyE * 4 + i;
            int swz = 4 * ((r >> 3) & 7);
#pragma unroll
            for (int j = 0; j < 4; j++) {
                int c = txE * 4 + j;
                float2 f = unpack2f(e2[i][j]);
                float v = f.x + f.y + b1[cg0 + c];
                Es[r * 40 + (c ^ swz)] = fmaxf(v, 0.f);
            }
        }
        __syncthreads();
        // ---- micro: acc += Es(128x32) @ F2(64x32)^T, rows tyM*8.., cols txM*4.. ----
#pragma unroll
        for (int kk = 0; kk < 32; kk += 2) {
            ull e[8], fv[4];
#pragma unroll
            for (int i = 0; i < 8; i++)
                e[i] = *(const ull*)&Es[(tyM * 8 + i) * 40 + (kk ^ eswM)];
#pragma unroll
            for (int j = 0; j < 4; j++)
                fv[j] = *(const ull*)&F2[(txM * 4 + j) * 36 + (kk ^ fswM)];
#pragma unroll
            for (int i = 0; i < 8; i++)
#pragma unroll
                for (int j = 0; j < 4; j++) ffma2(acc2[i][j], e[i], fv[j]);
        }
    }
#pragma unroll
    for (int i = 0; i < 8; i++)
#pragma unroll
        for (int j = 0; j < 4; j++) {
            float2 f = unpack2f(acc2[i][j]);
            part[((size_t)s * NROWS + m0 + tyM * 8 + i) * 64 + txM * 4 + j] = f.x + f.y;
        }
}

// ---------------- reduce partials -> emb, then XP = emb@w1i^T + b1c ----------------
__global__ void __launch_bounds__(256) reduce_xp(const float* __restrict__ fc7_b,
                                                 const float* __restrict__ w1i) {
    __shared__ __align__(16) float embS[32][66];
    const int tid = threadIdx.x;
    const int r0 = blockIdx.x * 32;
    for (int idx = tid; idx < 32 * 64; idx += 256) {
        int r = idx >> 6, n = idx & 63;
        float s = fc7_b[n];
#pragma unroll
        for (int ss = 0; ss < SPLITS; ss++)
            s += g_part[((size_t)ss * NROWS + r0 + r) * 64 + n];
        embS[r][n] = fmaxf(s, 0.f);
    }
    __syncthreads();
    ull w[32];
#pragma unroll
    for (int k = 0; k < 32; k++)
        w[k] = pack2f(w1i[tid * 64 + 2 * k], w1i[tid * 64 + 2 * k + 1]);
    const float bias = g_b1c[tid];
    for (int r = 0; r < 32; r++) {
        ull acc = pack2f(bias, 0.f);
#pragma unroll
        for (int k = 0; k < 32; k++) ffma2(acc, w[k], *(const ull*)&embS[r][2 * k]);
        float2 f = unpack2f(acc);
        g_XP[(size_t)(r0 + r) * 256 + tid] = f.x + f.y;
    }
}

// ---------------- reduce fe partials; gates1f = fe@w1i^T + h1@w1h^T + b1c -> g_XP ----------------
__global__ void __launch_bounds__(256) reduce_gates(const float* __restrict__ fc7_b,
                                                    const float* __restrict__ w1i,
                                                    const float* __restrict__ w1h) {
    __shared__ __align__(16) float feS[32][66];
    __shared__ __align__(16) float h1S[32][66];
    const int tid = threadIdx.x;
    const int r0 = blockIdx.x * 32;
    for (int idx = tid; idx < 32 * 64; idx += 256) {
        int r = idx >> 6, n = idx & 63;
        float s = fc7_b[n];
#pragma unroll
        for (int ss = 0; ss < SPLITS; ss++)
            s += g_part[((size_t)ss * NROWS + r0 + r) * 64 + n];
        feS[r][n] = fmaxf(s, 0.f);
        h1S[r][n] = g_states[(size_t)(r0 + r) * 192 + n];
    }
    __syncthreads();
    ull wi[32], wh[32];
#pragma unroll
    for (int k = 0; k < 32; k++) {
        wi[k] = pack2f(w1i[tid * 64 + 2 * k], w1i[tid * 64 + 2 * k + 1]);
        wh[k] = pack2f(w1h[tid * 64 + 2 * k], w1h[tid * 64 + 2 * k + 1]);
    }
    const float bias = g_b1c[tid];
    for (int r = 0; r < 32; r++) {
        ull acc = pack2f(bias, 0.f);
#pragma unroll
        for (int k = 0; k < 32; k++) ffma2(acc, wi[k], *(const ull*)&feS[r][2 * k]);
#pragma unroll
        for (int k = 0; k < 32; k++) ffma2(acc, wh[k], *(const ull*)&h1S[r][2 * k]);
        float2 f = unpack2f(acc);
        g_XP[(size_t)(r0 + r) * 256 + tid] = f.x + f.y;
    }
}

// ---------------- pipelined LSTM scan: lstm1(t) and lstm2(t-1) concurrently ----------------
__global__ void __launch_bounds__(384, 1) scan_kernel(
        const float* __restrict__ w1h, const float* __restrict__ w2i,
        const float* __restrict__ w2h, const float* __restrict__ b2i,
        const float* __restrict__ b2h) {
    __shared__ __align__(16) float h1s[64];
    __shared__ __align__(16) float h2s[32];
    __shared__ float act1[256], act2[128];
    const int tid = threadIdx.x;
    const int b = blockIdx.x;
    const float* xp = g_XP + (size_t)b * 65536;
    float* st = g_states + (size_t)b * 49152;

    ull wreg[48];
    float bc2 = 0.f, c1r = 0.f, c2r = 0.f;
    if (tid < 256) {
#pragma unroll
        for (int k = 0; k < 32; k++)
            wreg[k] = pack2f(w1h[tid * 64 + 2 * k], w1h[tid * 64 + 2 * k + 1]);
    } else {
        int g = tid - 256;
#pragma unroll
        for (int k = 0; k < 32; k++)
            wreg[k] = pack2f(w2i[g * 64 + 2 * k], w2i[g * 64 + 2 * k + 1]);
#pragma unroll
        for (int k = 0; k < 16; k++)
            wreg[32 + k] = pack2f(w2h[g * 32 + 2 * k], w2h[g * 32 + 2 * k + 1]);
        bc2 = b2i[g] + b2h[g];
    }
    if (tid < 64) h1s[tid] = 0.f;
    if (tid < 32) h2s[tid] = 0.f;
    __syncthreads();

    float xcur = (tid < 256) ? xp[tid] : 0.f;
    const bool t1tanh = (tid >= 128 && tid < 192);
    const bool t2tanh = (tid >= 320 && tid < 352);   // g2 in [64,96)

    for (int t = 0; t <= 256; t++) {
        float xnxt = 0.f;
        if (tid < 256 && t + 1 < 256) xnxt = xp[(t + 1) * 256 + tid];
        if (tid < 256) {
            if (t < 256) {
                ull acc = pack2f(xcur, 0.f);
#pragma unroll
                for (int k = 0; k < 32; k++) ffma2(acc, wreg[k], *(const ull*)&h1s[2 * k]);
                float2 f = unpack2f(acc);
                float g = f.x + f.y;
                act1[tid] = t1tanh ? tanh_f(g) : sig_f(g);
            }
        } else if (t > 0) {
            ull acc = pack2f(bc2, 0.f);
#pragma unroll
            for (int k = 0; k < 32; k++) ffma2(acc, wreg[k], *(const ull*)&h1s[2 * k]);
#pragma unroll
            for (int k = 0; k < 16; k++) ffma2(acc, wreg[32 + k], *(const ull*)&h2s[2 * k]);
            float2 f = unpack2f(acc);
            float g = f.x + f.y;
            act2[tid - 256] = t2tanh ? tanh_f(g) : sig_f(g);
        }
        __syncthreads();
        if (tid < 64) {
            if (t < 256) {
                float c = act1[64 + tid] * c1r + act1[tid] * act1[128 + tid];
                float h = act1[192 + tid] * tanh_f(c);
                c1r = c; h1s[tid] = h;
                st[t * 192 + tid] = h;
                st[t * 192 + 64 + tid] = c;
            }
        } else if (tid < 96 && t > 0) {
            int j = tid - 64, tp = t - 1;
            float c = act2[32 + j] * c2r + act2[j] * act2[64 + j];
            float h = act2[96 + j] * tanh_f(c);
            c2r = c; h2s[j] = h;
            st[tp * 192 + 128 + j] = h;
            st[tp * 192 + 160 + j] = c;
        }
        __syncthreads();
        xcur = xnxt;
    }
}

// ---------------- fused tail: flstm1 + gates2f + heads + fpool ----------------
__global__ void __launch_bounds__(128) tail_kernel(
        const float* __restrict__ fc8w, const float* __restrict__ fc8b,
        const float* __restrict__ fw, const float* __restrict__ fb,
        float* __restrict__ out, float* __restrict__ fpooled) {
    __shared__ float fh1[64], h2s[32], c2s[32], gs[128];
    const int tid = threadIdx.x;
    float wcat[96];
#pragma unroll
    for (int k = 0; k < 96; k++) wcat[k] = g_Wcat2[tid * 96 + k];
    const float b2 = g_b2c[tid];
    const int po = tid - 32;
    float fwr[32];
    if (po >= 0 && po < 90) {
#pragma unroll
        for (int k = 0; k < 32; k++) fwr[k] = fw[po * 32 + k];
    }
    const float w8 = (tid < 32) ? fc8w[tid] : 0.f;
    const float b8 = fc8b[0];
    const bool is_tanh2 = (tid >= 64 && tid < 96);

    for (int r = 0; r < 4; r++) {
        const int row = blockIdx.x * 4 + r;
        const float* xpf = g_XP + (size_t)row * 256;
        const float* st = g_states + (size_t)row * 192;
        if (tid < 64) {
            float i = sig_f(xpf[tid]);
            float f = sig_f(xpf[64 + tid]);
            float gg = tanh_f(xpf[128 + tid]);
            float o = sig_f(xpf[192 + tid]);
            float cn = f * st[64 + tid] + i * gg;
            fh1[tid] = o * tanh_f(cn);
        } else if (tid < 96) {
            h2s[tid - 64] = st[128 + (tid - 64)];
        } else {
            c2s[tid - 96] = st[160 + (tid - 96)];
        }
        __syncthreads();
        float a = b2;
#pragma unroll
        for (int k = 0; k < 64; k++) a += wcat[k] * fh1[k];
#pragma unroll
        for (int k = 0; k < 32; k++) a += wcat[64 + k] * h2s[k];
        gs[tid] = is_tanh2 ? tanh_f(a) : sig_f(a);
        __syncthreads();
        if (tid < 32) {
            float cn = gs[32 + tid] * c2s[tid] + gs[tid] * gs[64 + tid];
            float fh2 = gs[96 + tid] * tanh_f(cn);
            float v1 = h2s[tid] * w8;
            float v2 = fh2 * w8;
#pragma unroll
            for (int off = 16; off > 0; off >>= 1) {
                v1 += __shfl_down_sync(0xffffffffu, v1, off);
                v2 += __shfl_down_sync(0xffffffffu, v2, off);
            }
            if (tid == 0) {
                out[row] = sig_f(v1 + b8);
                out[NROWS + row] = sig_f(v2 + b8);
            }
        } else if (po < 90) {
            float s2 = fb[po];
#pragma unroll
            for (int k = 0; k < 32; k++) s2 += fwr[k] * h2s[k];
            fpooled[(size_t)row * 90 + po] = s2;
        }
        __syncthreads();
    }
}

// ---------------- host ----------------
extern "C" void kernel_launch(void* const* d_in, const int* in_sizes, int n_in,
                              void* d_out, int out_size) {
    const float* frames = (const float*)d_in[0];
    const float* spp_w  = (const float*)d_in[1];
    const float* spp_b  = (const float*)d_in[2];
    const float* fc7_w  = (const float*)d_in[3];
    const float* fc7_b  = (const float*)d_in[4];
    const float* w1i    = (const float*)d_in[5];
    const float* w1h    = (const float*)d_in[6];
    const float* b1i    = (const float*)d_in[7];
    const float* b1h    = (const float*)d_in[8];
    const float* w2i    = (const float*)d_in[9];
    const float* w2h    = (const float*)d_in[10];
    const float* b2i    = (const float*)d_in[11];
    const float* b2h    = (const float*)d_in[12];
    const float* fw     = (const float*)d_in[13];
    const float* fb     = (const float*)d_in[14];
    const float* fc8w   = (const float*)d_in[15];
    const float* fc8b   = (const float*)d_in[16];
    float* out = (float*)d_out;

    float *PART, *ST, *G, *CV;
    cudaGetSymbolAddress((void**)&PART, g_part);
    cudaGetSymbolAddress((void**)&ST, g_states);
    cudaGetSymbolAddress((void**)&G, g_G);
    cudaGetSymbolAddress((void**)&CV, g_cvec);

    const int SM1 = (128 * 92 + 32 * 90 + 64 * 36 + 128 * 40) * 4;   // 88320
    const int SM2 = (128 * 34 + 32 * 34 + 64 * 36 + 128 * 40) * 4;   // 51456
    cudaFuncSetAttribute(fused_mlp<90>, cudaFuncAttributeMaxDynamicSharedMemorySize, SM1);
    cudaFuncSetAttribute(fused_mlp<32>, cudaFuncAttributeMaxDynamicSharedMemorySize, SM2);

    float* pooled  = out + 2 * NROWS;
    float* fpooled = out + 2 * NROWS + NROWS * 90;

    spp_kernel<<<6144, 160>>>(frames, pooled);
    prep_kernel<<<530, 256>>>(spp_w, spp_b, fw, fb, b1i, b1h, w2i, w2h, b2i, b2h);
    fused_mlp<90><<<dim3(SPLITS, 16), 256, SM1>>>(pooled, 90, spp_w, spp_b, fc7_w, PART);
    reduce_xp<<<64, 256>>>(fc7_b, w1i);
    scan_kernel<<<8, 384>>>(w1h, w2i, w2h, b2i, b2h);
    fused_mlp<32><<<dim3(SPLITS, 16), 256, SM2>>>(ST + 128, 192, G, CV, fc7_w, PART);
    reduce_gates<<<64, 256>>>(fc7_b, w1i, w1h);
    tail_kernel<<<512, 128>>>(fc8w, fc8b, fw, fb, out, fpooled);
}

// round 5
// speedup vs baseline: 1.3679x; 1.0733x over previous
#include <cuda_runtime.h>
#include <cuda_bf16.h>
#include <math.h>

#define NROWS 2048
#define EMBED 4096
#define SPLITS 16

typedef unsigned long long ull;

__device__ __forceinline__ void ffma2(ull& d, ull a, ull b) {
    asm("fma.rn.f32x2 %0, %1, %2, %3;" : "=l"(d) : "l"(a), "l"(b), "l"(d));
}
__device__ __forceinline__ ull pack2f(float x, float y) {
    ull r; asm("mov.b64 %0, {%1, %2};" : "=l"(r) : "f"(x), "f"(y)); return r;
}
__device__ __forceinline__ float2 unpack2f(ull v) {
    float2 f; asm("mov.b64 {%0, %1}, %2;" : "=f"(f.x), "=f"(f.y) : "l"(v)); return f;
}

// ---------------- scratch ----------------
__device__ float g_part[SPLITS * NROWS * 64];
__device__ float g_XP[NROWS * 256];
__device__ float g_states[NROWS * 192];   // per row: h1[64] c1[64] h2[32] c2[32]
__device__ float g_G[EMBED * 32];
__device__ float g_cvec[EMBED];
__device__ float g_Wcat2[128 * 96];
__device__ float g_b1c[256];
__device__ float g_b2c[128];

__device__ __forceinline__ float sig_f(float x) {
    return __fdividef(1.0f, 1.0f + __expf(-x));
}
__device__ __forceinline__ float tanh_f(float x) {
    return __fdividef(2.0f, 1.0f + __expf(-2.0f * x)) - 1.0f;
}

// ---------------- SPP ----------------
__global__ void spp_kernel(const float* __restrict__ frames, float* __restrict__ pooled) {
    __shared__ float tmax[144];
    const int nc = blockIdx.x;
    const int n = nc / 3, c = nc % 3;
    const float* img = frames + (size_t)nc * 9216;
    const int tid = threadIdx.x;
    if (tid < 144) {
        const int ti = tid / 12, tj = tid % 12;
        const float* p = img + ti * 8 * 96 + tj * 8;
        float m = -3.402823466e38f;
#pragma unroll
        for (int r = 0; r < 8; r++) {
            float4 v0 = *(const float4*)(p + r * 96);
            float4 v1 = *(const float4*)(p + r * 96 + 4);
            m = fmaxf(m, fmaxf(fmaxf(v0.x, v0.y), fmaxf(v0.z, v0.w)));
            m = fmaxf(m, fmaxf(fmaxf(v1.x, v1.y), fmaxf(v1.z, v1.w)));
        }
        tmax[tid] = m;
    }
    __syncthreads();
    float* orow = pooled + (size_t)n * 90;
    if (tid < 16) {
        int i = tid / 4, j = tid % 4;
        float m = -3.402823466e38f;
        for (int a = 0; a < 3; a++) for (int b = 0; b < 3; b++)
            m = fmaxf(m, tmax[(i * 3 + a) * 12 + (j * 3 + b)]);
        orow[c * 16 + i * 4 + j] = m;
    } else if (tid < 25) {
        int q = tid - 16, i = q / 3, j = q % 3;
        float m = -3.402823466e38f;
        for (int a = 0; a < 4; a++) for (int b = 0; b < 4; b++)
            m = fmaxf(m, tmax[(i * 4 + a) * 12 + (j * 4 + b)]);
        orow[48 + c * 9 + i * 3 + j] = m;
    } else if (tid < 29) {
        int q = tid - 25, i = q / 2, j = q % 2;
        float m = -3.402823466e38f;
        for (int a = 0; a < 6; a++) for (int b = 0; b < 6; b++)
            m = fmaxf(m, tmax[(i * 6 + a) * 12 + (j * 6 + b)]);
        orow[75 + c * 4 + i * 2 + j] = m;
    } else if (tid == 29) {
        float m = -3.402823466e38f;
        for (int a = 0; a < 144; a++) m = fmaxf(m, tmax[a]);
        orow[87 + c] = m;
    }
}

// ---------------- prep: G = spp_w@fw, cvec, combined biases, Wcat2 ----------------
__global__ void prep_kernel(const float* __restrict__ spp_w, const float* __restrict__ spp_b,
                            const float* __restrict__ fw, const float* __restrict__ fb,
                            const float* __restrict__ b1i, const float* __restrict__ b1h,
                            const float* __restrict__ w2i, const float* __restrict__ w2h,
                            const float* __restrict__ b2i, const float* __restrict__ b2h) {
    const int blk = blockIdx.x, tid = threadIdx.x;
    if (blk < 512) {
        int o = blk * 256 + tid;
        int i = o >> 5, j = o & 31;
        float s = 0.f;
        for (int p = 0; p < 90; p++) s += spp_w[i * 90 + p] * fw[p * 32 + j];
        g_G[o] = s;
    } else if (blk < 528) {
        int i = (blk - 512) * 256 + tid;
        float s = spp_b[i];
        for (int p = 0; p < 90; p++) s += spp_w[i * 90 + p] * fb[p];
        g_cvec[i] = s;
    } else if (blk == 528) {
        g_b1c[tid] = b1i[tid] + b1h[tid];
        if (tid < 128) g_b2c[tid] = b2i[tid] + b2h[tid];
    } else if (blk == 529) {
        for (int idx = tid; idx < 12288; idx += 256) {
            int g = idx / 96, k = idx - g * 96;
            g_Wcat2[idx] = (k < 64) ? w2i[g * 64 + k] : w2h[g * 32 + (k - 64)];
        }
    }
}

// ---------------- fused two-layer MLP with split-K over the 4096 hidden dim ----------------
template<int KA>
__global__ void __launch_bounds__(256) fused_mlp(
        const float* __restrict__ A, int lda,
        const float* __restrict__ W1, const float* __restrict__ b1,
        const float* __restrict__ fc7, float* __restrict__ part) {
    constexpr int KAP = KA + 2;
    constexpr int WS  = (KA == 90) ? 90 : 34;
    constexpr int NW  = (32 * KA + 255) / 256;
    extern __shared__ float sm[];
    float* A2 = sm;                       // [128][KAP]
    float* W2 = A2 + 128 * KAP;           // [32][WS]
    float* F2 = W2 + 32 * WS;             // [64][36] swizzled
    float* Es = F2 + 64 * 36;             // [128][40] swizzled
    const int tid = threadIdx.x;
    const int s = blockIdx.x, m0 = blockIdx.y * 128;
    for (int idx = tid; idx < 128 * KA; idx += 256) {
        int r = idx / KA, p = idx - r * KA;
        A2[r * KAP + p] = A[(size_t)(m0 + r) * lda + p];
    }
    ull acc2[8][4];
#pragma unroll
    for (int i = 0; i < 8; i++)
#pragma unroll
        for (int j = 0; j < 4; j++) acc2[i][j] = 0ull;
    const int kbase = s * 256;
    const int txE = tid & 7, tyE = tid >> 3;
    const int txM = tid & 15, tyM = tid >> 4;
    const int eswM = 4 * (tyM & 7);
    const int fswM = 4 * (txM & 7);

    float pw[NW], pf[8];
#pragma unroll
    for (int i = 0; i < NW; i++) {
        int idx = tid + i * 256;
        if (idx < 32 * KA) pw[i] = W1[(size_t)(kbase + idx / KA) * KA + idx % KA];
    }
#pragma unroll
    for (int i = 0; i < 8; i++) {
        int idx = tid + i * 256;
        pf[i] = fc7[(size_t)(idx >> 5) * 4096 + kbase + (idx & 31)];
    }

    for (int kc = 0; kc < 256; kc += 32) {
        const int cg0 = kbase + kc;
        __syncthreads();
#pragma unroll
        for (int i = 0; i < NW; i++) {
            int idx = tid + i * 256;
            if (idx < 32 * KA) W2[(idx / KA) * WS + idx % KA] = pw[i];
        }
#pragma unroll
        for (int i = 0; i < 8; i++) {
            int idx = tid + i * 256;
            int n = idx >> 5, kk = idx & 31;
            F2[n * 36 + (kk ^ (4 * ((n >> 2) & 7)))] = pf[i];
        }
        __syncthreads();
        if (kc + 32 < 256) {
            const int ng0 = cg0 + 32;
#pragma unroll
            for (int i = 0; i < NW; i++) {
                int idx = tid + i * 256;
                if (idx < 32 * KA) pw[i] = W1[(size_t)(ng0 + idx / KA) * KA + idx % KA];
            }
#pragma unroll
            for (int i = 0; i < 8; i++) {
                int idx = tid + i * 256;
                pf[i] = fc7[(size_t)(idx >> 5) * 4096 + ng0 + (idx & 31)];
            }
        }
        // ---- E chunk: rows tyE*4.., cols txE*4.. ----
        ull e2[4][4];
#pragma unroll
        for (int i = 0; i < 4; i++)
#pragma unroll
            for (int j = 0; j < 4; j++) e2[i][j] = 0ull;
#pragma unroll 15
        for (int p = 0; p < KA; p += 2) {
            ull a0 = *(const ull*)&A2[(tyE * 4 + 0) * KAP + p];
            ull a1 = *(const ull*)&A2[(tyE * 4 + 1) * KAP + p];
            ull a2 = *(const ull*)&A2[(tyE * 4 + 2) * KAP + p];
            ull a3 = *(const ull*)&A2[(tyE * 4 + 3) * KAP + p];
            ull w0 = *(const ull*)&W2[(txE * 4 + 0) * WS + p];
            ull w1 = *(const ull*)&W2[(txE * 4 + 1) * WS + p];
            ull w2 = *(const ull*)&W2[(txE * 4 + 2) * WS + p];
            ull w3 = *(const ull*)&W2[(txE * 4 + 3) * WS + p];
            ffma2(e2[0][0], a0, w0); ffma2(e2[0][1], a0, w1);
            ffma2(e2[0][2], a0, w2); ffma2(e2[0][3], a0, w3);
            ffma2(e2[1][0], a1, w0); ffma2(e2[1][1], a1, w1);
            ffma2(e2[1][2], a1, w2); ffma2(e2[1][3], a1, w3);
            ffma2(e2[2][0], a2, w0); ffma2(e2[2][1], a2, w1);
            ffma2(e2[2][2], a2, w2); ffma2(e2[2][3], a2, w3);
            ffma2(e2[3][0], a3, w0); ffma2(e2[3][1], a3, w1);
            ffma2(e2[3][2], a3, w2); ffma2(e2[3][3], a3, w3);
        }
#pragma unroll
        for (int i = 0; i < 4; i++) {
            int r = tyE * 4 + i;
            int swz = 4 * ((r >> 3) & 7);
#pragma unroll
            for (int j = 0; j < 4; j++) {
                int c = txE * 4 + j;
                float2 f = unpack2f(e2[i][j]);
                float v = f.x + f.y + b1[cg0 + c];
                Es[r * 40 + (c ^ swz)] = fmaxf(v, 0.f);
            }
        }
        __syncthreads();
        // ---- micro: acc += Es(128x32) @ F2(64x32)^T ----
#pragma unroll
        for (int kk = 0; kk < 32; kk += 2) {
            ull e[8], fv[4];
#pragma unroll
            for (int i = 0; i < 8; i++)
                e[i] = *(const ull*)&Es[(tyM * 8 + i) * 40 + (kk ^ eswM)];
#pragma unroll
            for (int j = 0; j < 4; j++)
                fv[j] = *(const ull*)&F2[(txM * 4 + j) * 36 + (kk ^ fswM)];
#pragma unroll
            for (int i = 0; i < 8; i++)
#pragma unroll
                for (int j = 0; j < 4; j++) ffma2(acc2[i][j], e[i], fv[j]);
        }
    }
#pragma unroll
    for (int i = 0; i < 8; i++)
#pragma unroll
        for (int j = 0; j < 4; j++) {
            float2 f = unpack2f(acc2[i][j]);
            part[((size_t)s * NROWS + m0 + tyM * 8 + i) * 64 + txM * 4 + j] = f.x + f.y;
        }
}

// ---------------- reduce partials -> emb, then XP = emb@w1i^T + b1c ----------------
// grid 128, 16 rows/block
__global__ void __launch_bounds__(256) reduce_xp(const float* __restrict__ fc7_b,
                                                 const float* __restrict__ w1i) {
    __shared__ __align__(16) float embS[16][66];
    const int tid = threadIdx.x;
    const int r0 = blockIdx.x * 16;
    {
        int r = tid >> 4, ng = tid & 15;
        float4 acc = *(const float4*)&fc7_b[ng * 4];
#pragma unroll
        for (int ss = 0; ss < SPLITS; ss++) {
            float4 v = *(const float4*)&g_part[((size_t)ss * NROWS + r0 + r) * 64 + ng * 4];
            acc.x += v.x; acc.y += v.y; acc.z += v.z; acc.w += v.w;
        }
        embS[r][ng * 4 + 0] = fmaxf(acc.x, 0.f);
        embS[r][ng * 4 + 1] = fmaxf(acc.y, 0.f);
        embS[r][ng * 4 + 2] = fmaxf(acc.z, 0.f);
        embS[r][ng * 4 + 3] = fmaxf(acc.w, 0.f);
    }
    __syncthreads();
    ull w[32];
#pragma unroll
    for (int k = 0; k < 32; k++)
        w[k] = pack2f(w1i[tid * 64 + 2 * k], w1i[tid * 64 + 2 * k + 1]);
    const float bias = g_b1c[tid];
    for (int r = 0; r < 16; r += 2) {
        ull a0 = pack2f(bias, 0.f), a1 = 0ull;
        ull c0 = pack2f(bias, 0.f), c1 = 0ull;
#pragma unroll
        for (int k = 0; k < 16; k++) {
            ffma2(a0, w[2 * k],     *(const ull*)&embS[r][4 * k]);
            ffma2(a1, w[2 * k + 1], *(const ull*)&embS[r][4 * k + 2]);
            ffma2(c0, w[2 * k],     *(const ull*)&embS[r + 1][4 * k]);
            ffma2(c1, w[2 * k + 1], *(const ull*)&embS[r + 1][4 * k + 2]);
        }
        float2 f0 = unpack2f(a0), f1 = unpack2f(a1);
        float2 g0 = unpack2f(c0), g1 = unpack2f(c1);
        g_XP[(size_t)(r0 + r) * 256 + tid]     = (f0.x + f0.y) + (f1.x + f1.y);
        g_XP[(size_t)(r0 + r + 1) * 256 + tid] = (g0.x + g0.y) + (g1.x + g1.y);
    }
}

// ---------------- reduce fe partials; gates1f = [fe|h1]@[w1i|w1h]^T + b1c -> g_XP ----------------
__global__ void __launch_bounds__(256) reduce_gates(const float* __restrict__ fc7_b,
                                                    const float* __restrict__ w1i,
                                                    const float* __restrict__ w1h) {
    __shared__ __align__(16) float S[16][132];   // [0:64)=fe, [64:128)=h1
    const int tid = threadIdx.x;
    const int r0 = blockIdx.x * 16;
    {
        int r = tid >> 4, ng = tid & 15;
        float4 acc = *(const float4*)&fc7_b[ng * 4];
#pragma unroll
        for (int ss = 0; ss < SPLITS; ss++) {
            float4 v = *(const float4*)&g_part[((size_t)ss * NROWS + r0 + r) * 64 + ng * 4];
            acc.x += v.x; acc.y += v.y; acc.z += v.z; acc.w += v.w;
        }
        S[r][ng * 4 + 0] = fmaxf(acc.x, 0.f);
        S[r][ng * 4 + 1] = fmaxf(acc.y, 0.f);
        S[r][ng * 4 + 2] = fmaxf(acc.z, 0.f);
        S[r][ng * 4 + 3] = fmaxf(acc.w, 0.f);
        float4 h = *(const float4*)&g_states[(size_t)(r0 + r) * 192 + ng * 4];
        *(float4*)&S[r][64 + ng * 4] = h;
    }
    __syncthreads();
    ull wc[64];
#pragma unroll
    for (int k = 0; k < 32; k++) {
        wc[k]      = pack2f(w1i[tid * 64 + 2 * k], w1i[tid * 64 + 2 * k + 1]);
        wc[32 + k] = pack2f(w1h[tid * 64 + 2 * k], w1h[tid * 64 + 2 * k + 1]);
    }
    const float bias = g_b1c[tid];
    for (int r = 0; r < 16; r += 2) {
        ull a0 = pack2f(bias, 0.f), a1 = 0ull;
        ull c0 = pack2f(bias, 0.f), c1 = 0ull;
#pragma unroll
        for (int k = 0; k < 32; k++) {
            ffma2(a0, wc[2 * k],     *(const ull*)&S[r][4 * k]);
            ffma2(a1, wc[2 * k + 1], *(const ull*)&S[r][4 * k + 2]);
            ffma2(c0, wc[2 * k],     *(const ull*)&S[r + 1][4 * k]);
            ffma2(c1, wc[2 * k + 1], *(const ull*)&S[r + 1][4 * k + 2]);
        }
        float2 f0 = unpack2f(a0), f1 = unpack2f(a1);
        float2 g0 = unpack2f(c0), g1 = unpack2f(c1);
        g_XP[(size_t)(r0 + r) * 256 + tid]     = (f0.x + f0.y) + (f1.x + f1.y);
        g_XP[(size_t)(r0 + r + 1) * 256 + tid] = (g0.x + g0.y) + (g1.x + g1.y);
    }
}

// ---------------- pipelined LSTM scan: lstm1(t) and lstm2(t-1) concurrently ----------------
__global__ void __launch_bounds__(384, 1) scan_kernel(
        const float* __restrict__ w1h, const float* __restrict__ w2i,
        const float* __restrict__ w2h, const float* __restrict__ b2i,
        const float* __restrict__ b2h) {
    __shared__ __align__(16) float h1s[64];
    __shared__ __align__(16) float h2s[32];
    __shared__ float act1[256], act2[128];
    const int tid = threadIdx.x;
    const int b = blockIdx.x;
    const float* xp = g_XP + (size_t)b * 65536;
    float* st = g_states + (size_t)b * 49152;

    ull wreg[48];
    float bc2 = 0.f, c1r = 0.f, c2r = 0.f;
    if (tid < 256) {
#pragma unroll
        for (int k = 0; k < 32; k++)
            wreg[k] = pack2f(w1h[tid * 64 + 2 * k], w1h[tid * 64 + 2 * k + 1]);
    } else {
        int g = tid - 256;
#pragma unroll
        for (int k = 0; k < 32; k++)
            wreg[k] = pack2f(w2i[g * 64 + 2 * k], w2i[g * 64 + 2 * k + 1]);
#pragma unroll
        for (int k = 0; k < 16; k++)
            wreg[32 + k] = pack2f(w2h[g * 32 + 2 * k], w2h[g * 32 + 2 * k + 1]);
        bc2 = b2i[g] + b2h[g];
    }
    if (tid < 64) h1s[tid] = 0.f;
    if (tid < 32) h2s[tid] = 0.f;
    __syncthreads();

    float xcur = (tid < 256) ? xp[tid] : 0.f;
    const bool t1tanh = (tid >= 128 && tid < 192);
    const bool t2tanh = (tid >= 320 && tid < 352);

    for (int t = 0; t <= 256; t++) {
        float xnxt = 0.f;
        if (tid < 256 && t + 1 < 256) xnxt = xp[(t + 1) * 256 + tid];
        if (tid < 256) {
            if (t < 256) {
                ull a0 = pack2f(xcur, 0.f), a1 = 0ull, a2 = 0ull, a3 = 0ull;
#pragma unroll
                for (int k = 0; k < 8; k++) {
                    ffma2(a0, wreg[4 * k + 0], *(const ull*)&h1s[8 * k + 0]);
                    ffma2(a1, wreg[4 * k + 1], *(const ull*)&h1s[8 * k + 2]);
                    ffma2(a2, wreg[4 * k + 2], *(const ull*)&h1s[8 * k + 4]);
                    ffma2(a3, wreg[4 * k + 3], *(const ull*)&h1s[8 * k + 6]);
                }
                float2 f0 = unpack2f(a0), f1 = unpack2f(a1);
                float2 f2 = unpack2f(a2), f3 = unpack2f(a3);
                float g = ((f0.x + f0.y) + (f1.x + f1.y)) + ((f2.x + f2.y) + (f3.x + f3.y));
                act1[tid] = t1tanh ? tanh_f(g) : sig_f(g);
            }
        } else if (t > 0) {
            ull a0 = pack2f(bc2, 0.f), a1 = 0ull, a2 = 0ull, a3 = 0ull;
#pragma unroll
            for (int k = 0; k < 8; k++) {
                ffma2(a0, wreg[4 * k + 0], *(const ull*)&h1s[8 * k + 0]);
                ffma2(a1, wreg[4 * k + 1], *(const ull*)&h1s[8 * k + 2]);
                ffma2(a2, wreg[4 * k + 2], *(const ull*)&h1s[8 * k + 4]);
                ffma2(a3, wreg[4 * k + 3], *(const ull*)&h1s[8 * k + 6]);
            }
#pragma unroll
            for (int k = 0; k < 4; k++) {
                ffma2(a0, wreg[32 + 4 * k + 0], *(const ull*)&h2s[8 * k + 0]);
                ffma2(a1, wreg[32 + 4 * k + 1], *(const ull*)&h2s[8 * k + 2]);
                ffma2(a2, wreg[32 + 4 * k + 2], *(const ull*)&h2s[8 * k + 4]);
                ffma2(a3, wreg[32 + 4 * k + 3], *(const ull*)&h2s[8 * k + 6]);
            }
            float2 f0 = unpack2f(a0), f1 = unpack2f(a1);
            float2 f2 = unpack2f(a2), f3 = unpack2f(a3);
            float g = ((f0.x + f0.y) + (f1.x + f1.y)) + ((f2.x + f2.y) + (f3.x + f3.y));
            act2[tid - 256] = t2tanh ? tanh_f(g) : sig_f(g);
        }
        __syncthreads();
        if (tid < 64) {
            if (t < 256) {
                float c = act1[64 + tid] * c1r + act1[tid] * act1[128 + tid];
                float h = act1[192 + tid] * tanh_f(c);
                c1r = c; h1s[tid] = h;
                st[t * 192 + tid] = h;
                st[t * 192 + 64 + tid] = c;
            }
        } else if (tid < 96 && t > 0) {
            int j = tid - 64, tp = t - 1;
            float c = act2[32 + j] * c2r + act2[j] * act2[64 + j];
            float h = act2[96 + j] * tanh_f(c);
            c2r = c; h2s[j] = h;
            st[tp * 192 + 128 + j] = h;
            st[tp * 192 + 160 + j] = c;
        }
        __syncthreads();
        xcur = xnxt;
    }
}

// ---------------- fused tail: flstm1 + gates2f + heads + fpool ----------------
__global__ void __launch_bounds__(128) tail_kernel(
        const float* __restrict__ fc8w, const float* __restrict__ fc8b,
        const float* __restrict__ fw, const float* __restrict__ fb,
        float* __restrict__ out, float* __restrict__ fpooled) {
    __shared__ float fh1[64], h2s[32], c2s[32], gs[128];
    const int tid = threadIdx.x;
    float wcat[96];
#pragma unroll
    for (int k = 0; k < 24; k++)
        *(float4*)&wcat[k * 4] = *(const float4*)&g_Wcat2[tid * 96 + k * 4];
    const float b2 = g_b2c[tid];
    const int po = tid - 32;
    float fwr[32];
    if (po >= 0 && po < 90) {
#pragma unroll
        for (int k = 0; k < 8; k++)
            *(float4*)&fwr[k * 4] = *(const float4*)&fw[po * 32 + k * 4];
    }
    const float w8 = (tid < 32) ? fc8w[tid] : 0.f;
    const float b8 = fc8b[0];
    const bool is_tanh2 = (tid >= 64 && tid < 96);

    for (int r = 0; r < 4; r++) {
        const int row = blockIdx.x * 4 + r;
        const float* xpf = g_XP + (size_t)row * 256;
        const float* st = g_states + (size_t)row * 192;
        if (tid < 64) {
            float i = sig_f(xpf[tid]);
            float f = sig_f(xpf[64 + tid]);
            float gg = tanh_f(xpf[128 + tid]);
            float o = sig_f(xpf[192 + tid]);
            float cn = f * st[64 + tid] + i * gg;
            fh1[tid] = o * tanh_f(cn);
        } else if (tid < 96) {
            h2s[tid - 64] = st[128 + (tid - 64)];
        } else {
            c2s[tid - 96] = st[160 + (tid - 96)];
        }
        __syncthreads();
        float a = b2;
#pragma unroll
        for (int k = 0; k < 64; k++) a += wcat[k] * fh1[k];
#pragma unroll
        for (int k = 0; k < 32; k++) a += wcat[64 + k] * h2s[k];
        gs[tid] = is_tanh2 ? tanh_f(a) : sig_f(a);
        __syncthreads();
        if (tid < 32) {
            float cn = gs[32 + tid] * c2s[tid] + gs[tid] * gs[64 + tid];
            float fh2 = gs[96 + tid] * tanh_f(cn);
            float v1 = h2s[tid] * w8;
            float v2 = fh2 * w8;
#pragma unroll
            for (int off = 16; off > 0; off >>= 1) {
                v1 += __shfl_down_sync(0xffffffffu, v1, off);
                v2 += __shfl_down_sync(0xffffffffu, v2, off);
            }
            if (tid == 0) {
                out[row] = sig_f(v1 + b8);
                out[NROWS + row] = sig_f(v2 + b8);
            }
        } else if (po < 90) {
            float s2 = fb[po];
#pragma unroll
            for (int k = 0; k < 32; k++) s2 += fwr[k] * h2s[k];
            fpooled[(size_t)row * 90 + po] = s2;
        }
        __syncthreads();
    }
}

// ---------------- host ----------------
extern "C" void kernel_launch(void* const* d_in, const int* in_sizes, int n_in,
                              void* d_out, int out_size) {
    const float* frames = (const float*)d_in[0];
    const float* spp_w  = (const float*)d_in[1];
    const float* spp_b  = (const float*)d_in[2];
    const float* fc7_w  = (const float*)d_in[3];
    const float* fc7_b  = (const float*)d_in[4];
    const float* w1i    = (const float*)d_in[5];
    const float* w1h    = (const float*)d_in[6];
    const float* b1i    = (const float*)d_in[7];
    const float* b1h    = (const float*)d_in[8];
    const float* w2i    = (const float*)d_in[9];
    const float* w2h    = (const float*)d_in[10];
    const float* b2i    = (const float*)d_in[11];
    const float* b2h    = (const float*)d_in[12];
    const float* fw     = (const float*)d_in[13];
    const float* fb     = (const float*)d_in[14];
    const float* fc8w   = (const float*)d_in[15];
    const float* fc8b   = (const float*)d_in[16];
    float* out = (float*)d_out;

    float *PART, *ST, *G, *CV;
    cudaGetSymbolAddress((void**)&PART, g_part);
    cudaGetSymbolAddress((void**)&ST, g_states);
    cudaGetSymbolAddress((void**)&G, g_G);
    cudaGetSymbolAddress((void**)&CV, g_cvec);

    const int SM1 = (128 * 92 + 32 * 90 + 64 * 36 + 128 * 40) * 4;
    const int SM2 = (128 * 34 + 32 * 34 + 64 * 36 + 128 * 40) * 4;
    cudaFuncSetAttribute(fused_mlp<90>, cudaFuncAttributeMaxDynamicSharedMemorySize, SM1);
    cudaFuncSetAttribute(fused_mlp<32>, cudaFuncAttributeMaxDynamicSharedMemorySize, SM2);

    float* pooled  = out + 2 * NROWS;
    float* fpooled = out + 2 * NROWS + NROWS * 90;

    spp_kernel<<<6144, 160>>>(frames, pooled);
    prep_kernel<<<530, 256>>>(spp_w, spp_b, fw, fb, b1i, b1h, w2i, w2h, b2i, b2h);
    fused_mlp<90><<<dim3(SPLITS, 16), 256, SM1>>>(pooled, 90, spp_w, spp_b, fc7_w, PART);
    reduce_xp<<<128, 256>>>(fc7_b, w1i);
    scan_kernel<<<8, 384>>>(w1h, w2i, w2h, b2i, b2h);
    fused_mlp<32><<<dim3(SPLITS, 16), 256, SM2>>>(ST + 128, 192, G, CV, fc7_w, PART);
    reduce_gates<<<128, 256>>>(fc7_b, w1i, w1h);
    tail_kernel<<<512, 128>>>(fc8w, fc8b, fw, fb, out, fpooled);
}

// round 6
// speedup vs baseline: 1.4085x; 1.0297x over previous
#include <cuda_runtime.h>
#include <cuda_bf16.h>
#include <math.h>

#define NROWS 2048
#define EMBED 4096
#define SPLITS 16

typedef unsigned long long ull;

__device__ __forceinline__ void ffma2(ull& d, ull a, ull b) {
    asm("fma.rn.f32x2 %0, %1, %2, %3;" : "=l"(d) : "l"(a), "l"(b), "l"(d));
}
__device__ __forceinline__ ull pack2f(float x, float y) {
    ull r; asm("mov.b64 %0, {%1, %2};" : "=l"(r) : "f"(x), "f"(y)); return r;
}
__device__ __forceinline__ float2 unpack2f(ull v) {
    float2 f; asm("mov.b64 {%0, %1}, %2;" : "=f"(f.x), "=f"(f.y) : "l"(v)); return f;
}

// ---------------- scratch ----------------
__device__ float g_part[SPLITS * NROWS * 64];
__device__ float g_XP[NROWS * 256];
__device__ float g_states[NROWS * 192];   // per row: h1[64] c1[64] h2[32] c2[32]
__device__ float g_G[EMBED * 32];
__device__ float g_cvec[EMBED];
__device__ float g_Wcat2[128 * 96];
__device__ float g_b1c[256];
__device__ float g_b2c[128];

__device__ __forceinline__ float sig_f(float x) {
    return __fdividef(1.0f, 1.0f + __expf(-x));
}
__device__ __forceinline__ float tanh_f(float x) {
    return __fdividef(2.0f, 1.0f + __expf(-2.0f * x)) - 1.0f;
}

// ---------------- merged SPP + prep ----------------
__global__ void spp_prep(const float* __restrict__ frames, float* __restrict__ pooled,
                         const float* __restrict__ spp_w, const float* __restrict__ spp_b,
                         const float* __restrict__ fw, const float* __restrict__ fb,
                         const float* __restrict__ b1i, const float* __restrict__ b1h,
                         const float* __restrict__ w2i, const float* __restrict__ w2h,
                         const float* __restrict__ b2i, const float* __restrict__ b2h) {
    const int tid = threadIdx.x;
    if (blockIdx.x < 6144) {
        __shared__ float tmax[144];
        const int nc = blockIdx.x;
        const int n = nc / 3, c = nc % 3;
        const float* img = frames + (size_t)nc * 9216;
        if (tid < 144) {
            const int ti = tid / 12, tj = tid % 12;
            const float* p = img + ti * 8 * 96 + tj * 8;
            float m = -3.402823466e38f;
#pragma unroll
            for (int r = 0; r < 8; r++) {
                float4 v0 = *(const float4*)(p + r * 96);
                float4 v1 = *(const float4*)(p + r * 96 + 4);
                m = fmaxf(m, fmaxf(fmaxf(v0.x, v0.y), fmaxf(v0.z, v0.w)));
                m = fmaxf(m, fmaxf(fmaxf(v1.x, v1.y), fmaxf(v1.z, v1.w)));
            }
            tmax[tid] = m;
        }
        __syncthreads();
        float* orow = pooled + (size_t)n * 90;
        if (tid < 16) {
            int i = tid / 4, j = tid % 4;
            float m = -3.402823466e38f;
            for (int a = 0; a < 3; a++) for (int b = 0; b < 3; b++)
                m = fmaxf(m, tmax[(i * 3 + a) * 12 + (j * 3 + b)]);
            orow[c * 16 + i * 4 + j] = m;
        } else if (tid < 25) {
            int q = tid - 16, i = q / 3, j = q % 3;
            float m = -3.402823466e38f;
            for (int a = 0; a < 4; a++) for (int b = 0; b < 4; b++)
                m = fmaxf(m, tmax[(i * 4 + a) * 12 + (j * 4 + b)]);
            orow[48 + c * 9 + i * 3 + j] = m;
        } else if (tid < 29) {
            int q = tid - 25, i = q / 2, j = q % 2;
            float m = -3.402823466e38f;
            for (int a = 0; a < 6; a++) for (int b = 0; b < 6; b++)
                m = fmaxf(m, tmax[(i * 6 + a) * 12 + (j * 6 + b)]);
            orow[75 + c * 4 + i * 2 + j] = m;
        } else if (tid == 29) {
            float m = -3.402823466e38f;
            for (int a = 0; a < 144; a++) m = fmaxf(m, tmax[a]);
            orow[87 + c] = m;
        }
        return;
    }
    const int blk = blockIdx.x - 6144;
    if (blk < 512) {
        int o = blk * 256 + tid;
        int i = o >> 5, j = o & 31;
        float s = 0.f;
        for (int p = 0; p < 90; p++) s += spp_w[i * 90 + p] * fw[p * 32 + j];
        g_G[o] = s;
    } else if (blk < 528) {
        int i = (blk - 512) * 256 + tid;
        float s = spp_b[i];
        for (int p = 0; p < 90; p++) s += spp_w[i * 90 + p] * fb[p];
        g_cvec[i] = s;
    } else if (blk == 528) {
        g_b1c[tid] = b1i[tid] + b1h[tid];
        if (tid < 128) g_b2c[tid] = b2i[tid] + b2h[tid];
    } else if (blk == 529) {
        for (int idx = tid; idx < 12288; idx += 256) {
            int g = idx / 96, k = idx - g * 96;
            g_Wcat2[idx] = (k < 64) ? w2i[g * 64 + k] : w2h[g * 32 + (k - 64)];
        }
    }
}

// ---------------- fused two-layer MLP with split-K over the 4096 hidden dim ----------------
template<int KA>
__global__ void __launch_bounds__(256) fused_mlp(
        const float* __restrict__ A, int lda,
        const float* __restrict__ W1, const float* __restrict__ b1,
        const float* __restrict__ fc7, float* __restrict__ part) {
    constexpr int KAP = (KA == 90) ? 90 : 34;   // 4*KAP mod 32 == 8 -> conflict-free row reads
    constexpr int WS  = (KA == 90) ? 90 : 34;
    constexpr int NW  = (32 * KA + 255) / 256;
    extern __shared__ float sm[];
    float* A2 = sm;                       // [128][KAP]
    float* W2 = A2 + 128 * KAP;           // [32][WS]
    float* F2 = W2 + 32 * WS;             // [64][36] swizzled
    float* Es = F2 + 64 * 36;             // [128][40] swizzled
    const int tid = threadIdx.x;
    const int s = blockIdx.x, m0 = blockIdx.y * 128;
    for (int idx = tid; idx < 128 * KA; idx += 256) {
        int r = idx / KA, p = idx - r * KA;
        A2[r * KAP + p] = A[(size_t)(m0 + r) * lda + p];
    }
    ull acc2[8][4];
#pragma unroll
    for (int i = 0; i < 8; i++)
#pragma unroll
        for (int j = 0; j < 4; j++) acc2[i][j] = 0ull;
    const int kbase = s * 256;
    const int txE = tid & 7, tyE = tid >> 3;
    const int txM = tid & 15, tyM = tid >> 4;
    const int eswM = 4 * (tyM & 7);
    const int fswM = 4 * (txM & 7);

    float pw[NW], pf[8];
#pragma unroll
    for (int i = 0; i < NW; i++) {
        int idx = tid + i * 256;
        if (idx < 32 * KA) pw[i] = W1[(size_t)(kbase + idx / KA) * KA + idx % KA];
    }
#pragma unroll
    for (int i = 0; i < 8; i++) {
        int idx = tid + i * 256;
        pf[i] = fc7[(size_t)(idx >> 5) * 4096 + kbase + (idx & 31)];
    }

    for (int kc = 0; kc < 256; kc += 32) {
        const int cg0 = kbase + kc;
        __syncthreads();
#pragma unroll
        for (int i = 0; i < NW; i++) {
            int idx = tid + i * 256;
            if (idx < 32 * KA) W2[(idx / KA) * WS + idx % KA] = pw[i];
        }
#pragma unroll
        for (int i = 0; i < 8; i++) {
            int idx = tid + i * 256;
            int n = idx >> 5, kk = idx & 31;
            F2[n * 36 + (kk ^ (4 * ((n >> 2) & 7)))] = pf[i];
        }
        __syncthreads();
        if (kc + 32 < 256) {
            const int ng0 = cg0 + 32;
#pragma unroll
            for (int i = 0; i < NW; i++) {
                int idx = tid + i * 256;
                if (idx < 32 * KA) pw[i] = W1[(size_t)(ng0 + idx / KA) * KA + idx % KA];
            }
#pragma unroll
            for (int i = 0; i < 8; i++) {
                int idx = tid + i * 256;
                pf[i] = fc7[(size_t)(idx >> 5) * 4096 + ng0 + (idx & 31)];
            }
        }
        // ---- E chunk: rows tyE*4.., cols txE*4.. ----
        ull e2[4][4];
#pragma unroll
        for (int i = 0; i < 4; i++)
#pragma unroll
            for (int j = 0; j < 4; j++) e2[i][j] = 0ull;
#pragma unroll 15
        for (int p = 0; p < KA; p += 2) {
            ull a0 = *(const ull*)&A2[(tyE * 4 + 0) * KAP + p];
            ull a1 = *(const ull*)&A2[(tyE * 4 + 1) * KAP + p];
            ull a2 = *(const ull*)&A2[(tyE * 4 + 2) * KAP + p];
            ull a3 = *(const ull*)&A2[(tyE * 4 + 3) * KAP + p];
            ull w0 = *(const ull*)&W2[(txE * 4 + 0) * WS + p];
            ull w1 = *(const ull*)&W2[(txE * 4 + 1) * WS + p];
            ull w2 = *(const ull*)&W2[(txE * 4 + 2) * WS + p];
            ull w3 = *(const ull*)&W2[(txE * 4 + 3) * WS + p];
            ffma2(e2[0][0], a0, w0); ffma2(e2[0][1], a0, w1);
            ffma2(e2[0][2], a0, w2); ffma2(e2[0][3], a0, w3);
            ffma2(e2[1][0], a1, w0); ffma2(e2[1][1], a1, w1);
            ffma2(e2[1][2], a1, w2); ffma2(e2[1][3], a1, w3);
            ffma2(e2[2][0], a2, w0); ffma2(e2[2][1], a2, w1);
            ffma2(e2[2][2], a2, w2); ffma2(e2[2][3], a2, w3);
            ffma2(e2[3][0], a3, w0); ffma2(e2[3][1], a3, w1);
            ffma2(e2[3][2], a3, w2); ffma2(e2[3][3], a3, w3);
        }
#pragma unroll
        for (int i = 0; i < 4; i++) {
            int r = tyE * 4 + i;
            int swz = 4 * ((r >> 3) & 7);
#pragma unroll
            for (int j = 0; j < 4; j++) {
                int c = txE * 4 + j;
                float2 f = unpack2f(e2[i][j]);
                float v = f.x + f.y + b1[cg0 + c];
                Es[r * 40 + (c ^ swz)] = fmaxf(v, 0.f);
            }
        }
        __syncthreads();
        // ---- micro: acc += Es(128x32) @ F2(64x32)^T ----
#pragma unroll
        for (int kk = 0; kk < 32; kk += 2) {
            ull e[8], fv[4];
#pragma unroll
            for (int i = 0; i < 8; i++)
                e[i] = *(const ull*)&Es[(tyM * 8 + i) * 40 + (kk ^ eswM)];
#pragma unroll
            for (int j = 0; j < 4; j++)
                fv[j] = *(const ull*)&F2[(txM * 4 + j) * 36 + (kk ^ fswM)];
#pragma unroll
            for (int i = 0; i < 8; i++)
#pragma unroll
                for (int j = 0; j < 4; j++) ffma2(acc2[i][j], e[i], fv[j]);
        }
    }
#pragma unroll
    for (int i = 0; i < 8; i++)
#pragma unroll
        for (int j = 0; j < 4; j++) {
            float2 f = unpack2f(acc2[i][j]);
            part[((size_t)s * NROWS + m0 + tyM * 8 + i) * 64 + txM * 4 + j] = f.x + f.y;
        }
}

// ---------------- reduce partials -> emb, then XP = emb@w1i^T + b1c ----------------
// weights staged coalesced into smem, then per-thread rows read from padded smem.
__global__ void __launch_bounds__(256) reduce_xp(const float* __restrict__ fc7_b,
                                                 const float* __restrict__ w1i) {
    extern __shared__ float dsm[];
    float* wS   = dsm;              // [256][66]
    float* embS = dsm + 256 * 66;   // [16][66]
    const int tid = threadIdx.x;
    const int r0 = blockIdx.x * 16;
    {
        int r = tid >> 4, ng = tid & 15;
        float4 acc = *(const float4*)&fc7_b[ng * 4];
#pragma unroll
        for (int ss = 0; ss < SPLITS; ss++) {
            float4 v = *(const float4*)&g_part[((size_t)ss * NROWS + r0 + r) * 64 + ng * 4];
            acc.x += v.x; acc.y += v.y; acc.z += v.z; acc.w += v.w;
        }
        embS[r * 66 + ng * 4 + 0] = fmaxf(acc.x, 0.f);
        embS[r * 66 + ng * 4 + 1] = fmaxf(acc.y, 0.f);
        embS[r * 66 + ng * 4 + 2] = fmaxf(acc.z, 0.f);
        embS[r * 66 + ng * 4 + 3] = fmaxf(acc.w, 0.f);
    }
    for (int idx = tid; idx < 16384; idx += 256)
        wS[(idx >> 6) * 66 + (idx & 63)] = w1i[idx];
    __syncthreads();
    ull w[32];
#pragma unroll
    for (int k = 0; k < 32; k++) w[k] = *(const ull*)&wS[tid * 66 + 2 * k];
    const float bias = g_b1c[tid];
    for (int r = 0; r < 16; r += 2) {
        ull a0 = pack2f(bias, 0.f), a1 = 0ull;
        ull c0 = pack2f(bias, 0.f), c1 = 0ull;
#pragma unroll
        for (int k = 0; k < 16; k++) {
            ffma2(a0, w[2 * k],     *(const ull*)&embS[r * 66 + 4 * k]);
            ffma2(a1, w[2 * k + 1], *(const ull*)&embS[r * 66 + 4 * k + 2]);
            ffma2(c0, w[2 * k],     *(const ull*)&embS[(r + 1) * 66 + 4 * k]);
            ffma2(c1, w[2 * k + 1], *(const ull*)&embS[(r + 1) * 66 + 4 * k + 2]);
        }
        float2 f0 = unpack2f(a0), f1 = unpack2f(a1);
        float2 g0 = unpack2f(c0), g1 = unpack2f(c1);
        g_XP[(size_t)(r0 + r) * 256 + tid]     = (f0.x + f0.y) + (f1.x + f1.y);
        g_XP[(size_t)(r0 + r + 1) * 256 + tid] = (g0.x + g0.y) + (g1.x + g1.y);
    }
}

// ---------------- reduce fe partials; gates1f = [fe|h1]@[w1i|w1h]^T + b1c -> g_XP ----------------
__global__ void __launch_bounds__(256) reduce_gates(const float* __restrict__ fc7_b,
                                                    const float* __restrict__ w1i,
                                                    const float* __restrict__ w1h) {
    extern __shared__ float dsm[];
    float* wS = dsm;                // [256][130]  [0:64)=w1i row, [64:128)=w1h row
    float* S  = dsm + 256 * 130;    // [16][132]   [0:64)=fe, [64:128)=h1
    const int tid = threadIdx.x;
    const int r0 = blockIdx.x * 16;
    {
        int r = tid >> 4, ng = tid & 15;
        float4 acc = *(const float4*)&fc7_b[ng * 4];
#pragma unroll
        for (int ss = 0; ss < SPLITS; ss++) {
            float4 v = *(const float4*)&g_part[((size_t)ss * NROWS + r0 + r) * 64 + ng * 4];
            acc.x += v.x; acc.y += v.y; acc.z += v.z; acc.w += v.w;
        }
        S[r * 132 + ng * 4 + 0] = fmaxf(acc.x, 0.f);
        S[r * 132 + ng * 4 + 1] = fmaxf(acc.y, 0.f);
        S[r * 132 + ng * 4 + 2] = fmaxf(acc.z, 0.f);
        S[r * 132 + ng * 4 + 3] = fmaxf(acc.w, 0.f);
        float4 h = *(const float4*)&g_states[(size_t)(r0 + r) * 192 + ng * 4];
        *(float4*)&S[r * 132 + 64 + ng * 4] = h;
    }
    for (int idx = tid; idx < 16384; idx += 256) {
        wS[(idx >> 6) * 130 + (idx & 63)]      = w1i[idx];
        wS[(idx >> 6) * 130 + 64 + (idx & 63)] = w1h[idx];
    }
    __syncthreads();
    ull wc[64];
#pragma unroll
    for (int k = 0; k < 64; k++) wc[k] = *(const ull*)&wS[tid * 130 + 2 * k];
    const float bias = g_b1c[tid];
    for (int r = 0; r < 16; r += 2) {
        ull a0 = pack2f(bias, 0.f), a1 = 0ull;
        ull c0 = pack2f(bias, 0.f), c1 = 0ull;
#pragma unroll
        for (int k = 0; k < 32; k++) {
            ffma2(a0, wc[2 * k],     *(const ull*)&S[r * 132 + 4 * k]);
            ffma2(a1, wc[2 * k + 1], *(const ull*)&S[r * 132 + 4 * k + 2]);
            ffma2(c0, wc[2 * k],     *(const ull*)&S[(r + 1) * 132 + 4 * k]);
            ffma2(c1, wc[2 * k + 1], *(const ull*)&S[(r + 1) * 132 + 4 * k + 2]);
        }
        float2 f0 = unpack2f(a0), f1 = unpack2f(a1);
        float2 g0 = unpack2f(c0), g1 = unpack2f(c1);
        g_XP[(size_t)(r0 + r) * 256 + tid]     = (f0.x + f0.y) + (f1.x + f1.y);
        g_XP[(size_t)(r0 + r + 1) * 256 + tid] = (g0.x + g0.y) + (g1.x + g1.y);
    }
}

// ---------------- pipelined LSTM scan: lstm1(t) and lstm2(t-1) concurrently ----------------
__global__ void __launch_bounds__(384, 1) scan_kernel(
        const float* __restrict__ w1h, const float* __restrict__ w2i,
        const float* __restrict__ w2h, const float* __restrict__ b2i,
        const float* __restrict__ b2h) {
    __shared__ __align__(16) float h1s[64];
    __shared__ __align__(16) float h2s[32];
    __shared__ float act1[256], act2[128];
    const int tid = threadIdx.x;
    const int b = blockIdx.x;
    const float* xp = g_XP + (size_t)b * 65536;
    float* st = g_states + (size_t)b * 49152;

    ull wreg[48];
    float bc2 = 0.f, c1r = 0.f, c2r = 0.f;
    if (tid < 256) {
#pragma unroll
        for (int k = 0; k < 32; k++)
            wreg[k] = pack2f(w1h[tid * 64 + 2 * k], w1h[tid * 64 + 2 * k + 1]);
    } else {
        int g = tid - 256;
#pragma unroll
        for (int k = 0; k < 32; k++)
            wreg[k] = pack2f(w2i[g * 64 + 2 * k], w2i[g * 64 + 2 * k + 1]);
#pragma unroll
        for (int k = 0; k < 16; k++)
            wreg[32 + k] = pack2f(w2h[g * 32 + 2 * k], w2h[g * 32 + 2 * k + 1]);
        bc2 = b2i[g] + b2h[g];
    }
    if (tid < 64) h1s[tid] = 0.f;
    if (tid < 32) h2s[tid] = 0.f;
    __syncthreads();

    float xcur = 0.f, x1 = 0.f;
    if (tid < 256) { xcur = xp[tid]; x1 = xp[256 + tid]; }
    const bool t1tanh = (tid >= 128 && tid < 192);
    const bool t2tanh = (tid >= 320 && tid < 352);

    for (int t = 0; t <= 256; t++) {
        float x2 = 0.f;
        if (tid < 256 && t + 2 < 256) x2 = xp[(t + 2) * 256 + tid];
        if (tid < 256) {
            if (t < 256) {
                ull a0 = pack2f(xcur, 0.f), a1 = 0ull, a2 = 0ull, a3 = 0ull;
#pragma unroll
                for (int k = 0; k < 8; k++) {
                    ffma2(a0, wreg[4 * k + 0], *(const ull*)&h1s[8 * k + 0]);
                    ffma2(a1, wreg[4 * k + 1], *(const ull*)&h1s[8 * k + 2]);
                    ffma2(a2, wreg[4 * k + 2], *(const ull*)&h1s[8 * k + 4]);
                    ffma2(a3, wreg[4 * k + 3], *(const ull*)&h1s[8 * k + 6]);
                }
                float2 f0 = unpack2f(a0), f1 = unpack2f(a1);
                float2 f2 = unpack2f(a2), f3 = unpack2f(a3);
                float g = ((f0.x + f0.y) + (f1.x + f1.y)) + ((f2.x + f2.y) + (f3.x + f3.y));
                act1[tid] = t1tanh ? tanh_f(g) : sig_f(g);
            }
        } else if (t > 0) {
            ull a0 = pack2f(bc2, 0.f), a1 = 0ull, a2 = 0ull, a3 = 0ull;
#pragma unroll
            for (int k = 0; k < 8; k++) {
                ffma2(a0, wreg[4 * k + 0], *(const ull*)&h1s[8 * k + 0]);
                ffma2(a1, wreg[4 * k + 1], *(const ull*)&h1s[8 * k + 2]);
                ffma2(a2, wreg[4 * k + 2], *(const ull*)&h1s[8 * k + 4]);
                ffma2(a3, wreg[4 * k + 3], *(const ull*)&h1s[8 * k + 6]);
            }
#pragma unroll
            for (int k = 0; k < 4; k++) {
                ffma2(a0, wreg[32 + 4 * k + 0], *(const ull*)&h2s[8 * k + 0]);
                ffma2(a1, wreg[32 + 4 * k + 1], *(const ull*)&h2s[8 * k + 2]);
                ffma2(a2, wreg[32 + 4 * k + 2], *(const ull*)&h2s[8 * k + 4]);
                ffma2(a3, wreg[32 + 4 * k + 3], *(const ull*)&h2s[8 * k + 6]);
            }
            float2 f0 = unpack2f(a0), f1 = unpack2f(a1);
            float2 f2 = unpack2f(a2), f3 = unpack2f(a3);
            float g = ((f0.x + f0.y) + (f1.x + f1.y)) + ((f2.x + f2.y) + (f3.x + f3.y));
            act2[tid - 256] = t2tanh ? tanh_f(g) : sig_f(g);
        }
        __syncthreads();
        if (tid < 64) {
            if (t < 256) {
                float c = act1[64 + tid] * c1r + act1[tid] * act1[128 + tid];
                float h = act1[192 + tid] * tanh_f(c);
                c1r = c; h1s[tid] = h;
                st[t * 192 + tid] = h;
                st[t * 192 + 64 + tid] = c;
            }
        } else if (tid < 96 && t > 0) {
            int j = tid - 64, tp = t - 1;
            float c = act2[32 + j] * c2r + act2[j] * act2[64 + j];
            float h = act2[96 + j] * tanh_f(c);
            c2r = c; h2s[j] = h;
            st[tp * 192 + 128 + j] = h;
            st[tp * 192 + 160 + j] = c;
        }
        __syncthreads();
        xcur = x1; x1 = x2;
    }
}

// ---------------- fused tail: flstm1 + gates2f + heads + fpool ----------------
// 128 blocks x 16 rows; weights staged coalesced in smem.
__global__ void __launch_bounds__(128) tail_kernel(
        const float* __restrict__ fc8w, const float* __restrict__ fc8b,
        const float* __restrict__ fw, const float* __restrict__ fb,
        float* __restrict__ out, float* __restrict__ fpooled) {
    extern __shared__ float dsm[];
    float* wcS = dsm;               // [128][98]
    float* fwS = dsm + 128 * 98;    // [90][34]
    __shared__ float fh1[64], h2s[32], c2s[32], gs[128];
    const int tid = threadIdx.x;
    for (int idx = tid; idx < 12288; idx += 128)
        wcS[(idx / 96) * 98 + idx % 96] = g_Wcat2[idx];
    for (int idx = tid; idx < 2880; idx += 128)
        fwS[(idx >> 5) * 34 + (idx & 31)] = fw[idx];
    __syncthreads();
    float wcat[96];
#pragma unroll
    for (int k = 0; k < 96; k++) wcat[k] = wcS[tid * 98 + k];
    const float b2 = g_b2c[tid];
    const int po = tid - 32;
    float fwr[32];
    if (po >= 0 && po < 90) {
#pragma unroll
        for (int k = 0; k < 32; k++) fwr[k] = fwS[po * 34 + k];
    }
    const float w8 = (tid < 32) ? fc8w[tid] : 0.f;
    const float b8 = fc8b[0];
    const bool is_tanh2 = (tid >= 64 && tid < 96);

    for (int r = 0; r < 16; r++) {
        const int row = blockIdx.x * 16 + r;
        const float* xpf = g_XP + (size_t)row * 256;
        const float* st = g_states + (size_t)row * 192;
        if (tid < 64) {
            float i = sig_f(xpf[tid]);
            float f = sig_f(xpf[64 + tid]);
            float gg = tanh_f(xpf[128 + tid]);
            float o = sig_f(xpf[192 + tid]);
            float cn = f * st[64 + tid] + i * gg;
            fh1[tid] = o * tanh_f(cn);
        } else if (tid < 96) {
            h2s[tid - 64] = st[128 + (tid - 64)];
        } else {
            c2s[tid - 96] = st[160 + (tid - 96)];
        }
        __syncthreads();
        float a = b2;
#pragma unroll
        for (int k = 0; k < 64; k++) a += wcat[k] * fh1[k];
#pragma unroll
        for (int k = 0; k < 32; k++) a += wcat[64 + k] * h2s[k];
        gs[tid] = is_tanh2 ? tanh_f(a) : sig_f(a);
        __syncthreads();
        if (tid < 32) {
            float cn = gs[32 + tid] * c2s[tid] + gs[tid] * gs[64 + tid];
            float fh2 = gs[96 + tid] * tanh_f(cn);
            float v1 = h2s[tid] * w8;
            float v2 = fh2 * w8;
#pragma unroll
            for (int off = 16; off > 0; off >>= 1) {
                v1 += __shfl_down_sync(0xffffffffu, v1, off);
                v2 += __shfl_down_sync(0xffffffffu, v2, off);
            }
            if (tid == 0) {
                out[row] = sig_f(v1 + b8);
                out[NROWS + row] = sig_f(v2 + b8);
            }
        } else if (po < 90) {
            float s2 = fb[po];
#pragma unroll
            for (int k = 0; k < 32; k++) s2 += fwr[k] * h2s[k];
            fpooled[(size_t)row * 90 + po] = s2;
        }
        __syncthreads();
    }
}

// ---------------- host ----------------
extern "C" void kernel_launch(void* const* d_in, const int* in_sizes, int n_in,
                              void* d_out, int out_size) {
    const float* frames = (const float*)d_in[0];
    const float* spp_w  = (const float*)d_in[1];
    const float* spp_b  = (const float*)d_in[2];
    const float* fc7_w  = (const float*)d_in[3];
    const float* fc7_b  = (const float*)d_in[4];
    const float* w1i    = (const float*)d_in[5];
    const float* w1h    = (const float*)d_in[6];
    const float* b1i    = (const float*)d_in[7];
    const float* b1h    = (const float*)d_in[8];
    const float* w2i    = (const float*)d_in[9];
    const float* w2h    = (const float*)d_in[10];
    const float* b2i    = (const float*)d_in[11];
    const float* b2h    = (const float*)d_in[12];
    const float* fw     = (const float*)d_in[13];
    const float* fb     = (const float*)d_in[14];
    const float* fc8w   = (const float*)d_in[15];
    const float* fc8b   = (const float*)d_in[16];
    float* out = (float*)d_out;

    float *PART, *ST, *G, *CV;
    cudaGetSymbolAddress((void**)&PART, g_part);
    cudaGetSymbolAddress((void**)&ST, g_states);
    cudaGetSymbolAddress((void**)&G, g_G);
    cudaGetSymbolAddress((void**)&CV, g_cvec);

    const int SM1 = (128 * 90 + 32 * 90 + 64 * 36 + 128 * 40) * 4;
    const int SM2 = (128 * 34 + 32 * 34 + 64 * 36 + 128 * 40) * 4;
    const int SMRX = (256 * 66 + 16 * 66) * 4;
    const int SMRG = (256 * 130 + 16 * 132) * 4;
    const int SMT  = (128 * 98 + 90 * 34) * 4;
    cudaFuncSetAttribute(fused_mlp<90>, cudaFuncAttributeMaxDynamicSharedMemorySize, SM1);
    cudaFuncSetAttribute(fused_mlp<32>, cudaFuncAttributeMaxDynamicSharedMemorySize, SM2);
    cudaFuncSetAttribute(reduce_xp, cudaFuncAttributeMaxDynamicSharedMemorySize, SMRX);
    cudaFuncSetAttribute(reduce_gates, cudaFuncAttributeMaxDynamicSharedMemorySize, SMRG);
    cudaFuncSetAttribute(tail_kernel, cudaFuncAttributeMaxDynamicSharedMemorySize, SMT);

    float* pooled  = out + 2 * NROWS;
    float* fpooled = out + 2 * NROWS + NROWS * 90;

    spp_prep<<<6674, 256>>>(frames, pooled, spp_w, spp_b, fw, fb,
                            b1i, b1h, w2i, w2h, b2i, b2h);
    fused_mlp<90><<<dim3(SPLITS, 16), 256, SM1>>>(pooled, 90, spp_w, spp_b, fc7_w, PART);
    reduce_xp<<<128, 256, SMRX>>>(fc7_b, w1i);
    scan_kernel<<<8, 384>>>(w1h, w2i, w2h, b2i, b2h);
    fused_mlp<32><<<dim3(SPLITS, 16), 256, SM2>>>(ST + 128, 192, G, CV, fc7_w, PART);
    reduce_gates<<<128, 256, SMRG>>>(fc7_b, w1i, w1h);
    tail_kernel<<<128, 128, SMT>>>(fc8w, fc8b, fw, fb, out, fpooled);
}